// round 10
// baseline (speedup 1.0000x reference)
#include <cuda_runtime.h>
#include <math.h>

#define BATCH 2
#define CDIM  96
#define DIN   192
#define NST   16
#define LSEQ  4096
#define NPIX  (BATCH*LSEQ)
#define NCH   (BATCH*4*DIN)
#define NCHUNK 16
#define CLEN  (LSEQ/NCHUNK)     // 256

typedef unsigned long long u64;

// ---------------- persistent device scratch ----------------
__device__ float  g_diff [NPIX*CDIM];
__device__ float  g_zs   [NPIX*DIN];
__device__ float  g_xm   [BATCH*DIN*LSEQ];
__device__ float  g_x0   [BATCH*DIN*LSEQ];
__device__ float  g_x1   [BATCH*DIN*LSEQ];
__device__ float  g_delta[BATCH*4*DIN*LSEQ];
__device__ float4 g_bb4  [BATCH*4*(LSEQ/4)*16];
__device__ float4 g_bc4  [BATCH*4*LSEQ*8];
__device__ float  g_y    [4*BATCH*DIN*LSEQ];
__device__ float  g_ysum [BATCH*DIN*LSEQ];
__device__ float  g_P    [NCH*NCHUNK*NST];
__device__ float  g_he   [NCH*NCHUNK*NST];
__device__ float  g_H    [NCH*NCHUNK*NST];

__device__ __forceinline__ float silu_f(float v){ return v / (1.f + __expf(-v)); }

// ---- packed fp32x2 helpers (sm_103a) ----
__device__ __forceinline__ u64 dup2(float v) {
    u64 r; asm("mov.b64 %0, {%1, %1};" : "=l"(r) : "f"(v)); return r;
}
__device__ __forceinline__ u64 fma2(u64 a, u64 b, u64 c) {
    u64 d; asm("fma.rn.f32x2 %0, %1, %2, %3;" : "=l"(d) : "l"(a), "l"(b), "l"(c)); return d;
}
__device__ __forceinline__ float2 unp2(u64 v) {
    float2 r; asm("mov.b64 {%0, %1}, %2;" : "=f"(r.x), "=f"(r.y) : "l"(v)); return r;
}

// ================= K1: diff + LN + in_proj GEMM (f32x2) =================
__global__ void k1_prologue(const float* __restrict__ x, const float* __restrict__ y,
                            const float* __restrict__ lnw, const float* __restrict__ lnb,
                            const float* __restrict__ wproj)
{
    extern __shared__ float sm[];
    float* A_s = sm;            // 96*64
    float* W_s = sm + 96*64;    // 96*128
    const int tid = threadIdx.x, lane = tid & 31, warp = tid >> 5;
    const int pix0 = blockIdx.x * 64;
    const int oc = blockIdx.y;

    for (int pp = 0; pp < 8; pp++) {
        const int p = warp * 8 + pp;
        const int base = (pix0 + p) * CDIM;
        float vv[3]; float s = 0.f, s2 = 0.f;
        #pragma unroll
        for (int j = 0; j < 3; j++) {
            int ch = lane + 32 * j;
            float d = fabsf(x[base + ch] - y[base + ch]);
            if (oc == 0) g_diff[base + ch] = d;
            vv[j] = d; s += d; s2 += d * d;
        }
        #pragma unroll
        for (int o = 16; o > 0; o >>= 1) {
            s  += __shfl_xor_sync(0xffffffffu, s,  o);
            s2 += __shfl_xor_sync(0xffffffffu, s2, o);
        }
        float mu = s * (1.f / 96.f);
        float var = s2 * (1.f / 96.f) - mu * mu;
        float rstd = rsqrtf(var + 1e-5f);
        #pragma unroll
        for (int j = 0; j < 3; j++) {
            int ch = lane + 32 * j;
            A_s[ch * 64 + p] = (vv[j] - mu) * rstd * lnw[ch] + lnb[ch];
        }
    }
    for (int i = tid; i < 96 * 128; i += 256) {
        int kk = i % 96, j = i / 96;
        W_s[kk * 128 + j] = wproj[(oc * 128 + j) * 96 + kk];
    }
    __syncthreads();

    const int pg = tid & 7;
    const int og = tid >> 3;
    const float4* W4 = (const float4*)W_s;

    u64 accp[4][4];
    #pragma unroll
    for (int a = 0; a < 4; a++)
        #pragma unroll
        for (int b = 0; b < 4; b++) accp[a][b] = 0ull;

    #pragma unroll 4
    for (int kk = 0; kk < 96; kk++) {
        const ulonglong2* ap = (const ulonglong2*)(A_s + kk * 64 + pg * 8);
        ulonglong2 a01 = ap[0], a23 = ap[1];          // 4 pixel-pairs
        float4 w = W4[kk * 32 + og];
        u64 wd[4] = {dup2(w.x), dup2(w.y), dup2(w.z), dup2(w.w)};
        #pragma unroll
        for (int jj = 0; jj < 4; jj++) {
            accp[jj][0] = fma2(wd[jj], a01.x, accp[jj][0]);
            accp[jj][1] = fma2(wd[jj], a01.y, accp[jj][1]);
            accp[jj][2] = fma2(wd[jj], a23.x, accp[jj][2]);
            accp[jj][3] = fma2(wd[jj], a23.y, accp[jj][3]);
        }
    }

    float acc[4][8];
    #pragma unroll
    for (int jj = 0; jj < 4; jj++) {
        #pragma unroll
        for (int pr = 0; pr < 4; pr++) {
            float2 f = unp2(accp[jj][pr]);
            acc[jj][pr * 2] = f.x; acc[jj][pr * 2 + 1] = f.y;
        }
    }

    const int jg0 = oc * 128 + og * 4;
    const int pixb = pix0 + pg * 8;
    const int bb = pixb >> 12, lb = pixb & 4095;
    if (jg0 + 3 < DIN) {
        #pragma unroll
        for (int jj = 0; jj < 4; jj++) {
            float* row = g_xm + (size_t)(bb * DIN + jg0 + jj) * LSEQ + lb;
            *(float4*)row       = make_float4(acc[jj][0], acc[jj][1], acc[jj][2], acc[jj][3]);
            *(float4*)(row + 4) = make_float4(acc[jj][4], acc[jj][5], acc[jj][6], acc[jj][7]);
        }
    } else {
        const int zc = jg0 - DIN;
        #pragma unroll
        for (int pi = 0; pi < 8; pi++) {
            float* zp = g_zs + (size_t)(pixb + pi) * DIN + zc;
            *(float4*)zp = make_float4(silu_f(acc[0][pi]), silu_f(acc[1][pi]),
                                       silu_f(acc[2][pi]), silu_f(acc[3][pi]));
        }
    }
}

// ================= K2: depthwise conv + silu =================
__global__ void k2_conv(const float* __restrict__ cw, const float* __restrict__ cb)
{
    __shared__ float tin [64 * 65];
    __shared__ float tout[64 * 65];
    const int tid = threadIdx.x;
    const int bd = blockIdx.x;
    const int d = bd % DIN;
    const float* src = g_xm + (size_t)bd * LSEQ;

    for (int t = tid; t < 1024; t += 256) {
        float4 v = ((const float4*)src)[t];
        int i = t * 4;
        int h = i >> 6, w = i & 63;
        float* p = &tin[h * 65 + w];
        p[0] = v.x; p[1] = v.y; p[2] = v.z; p[3] = v.w;
    }
    float wreg[9];
    #pragma unroll
    for (int i = 0; i < 9; i++) wreg[i] = cw[d * 9 + i];
    const float bias = cb[d];
    __syncthreads();

    float* dst0 = g_x0 + (size_t)bd * LSEQ;
    for (int t = tid; t < 4096; t += 256) {
        int h = t >> 6, w = t & 63;
        float acc = bias;
        #pragma unroll
        for (int dy = 0; dy < 3; dy++) {
            int hh = h + dy - 1;
            if (hh < 0 || hh > 63) continue;
            #pragma unroll
            for (int dx = 0; dx < 3; dx++) {
                int ww = w + dx - 1;
                if (ww < 0 || ww > 63) continue;
                acc = fmaf(tin[hh * 65 + ww], wreg[dy * 3 + dx], acc);
            }
        }
        float v = silu_f(acc);
        dst0[t] = v;
        tout[h * 65 + w] = v;
    }
    __syncthreads();

    float* dst1 = g_x1 + (size_t)bd * LSEQ;
    for (int t = tid; t < 4096; t += 256) {
        int w = t >> 6, h = t & 63;
        dst1[t] = tout[h * 65 + w];
    }
}

// ================= K3: x_proj + dt_proj + softplus (f32x2) =================
__global__ void k3_xproj(const float* __restrict__ xpw, const float* __restrict__ dtw,
                         const float* __restrict__ dtb)
{
    extern __shared__ float sm[];
    float* u_s  = sm;                         // 192*64
    float* wp_t = u_s + 192 * 64;             // 192*48
    float* xd_s = wp_t + 192 * 48;            // 38*65
    float* dw_s = xd_s + 38 * 65;             // 192*6
    float* db_s = dw_s + 192 * 6;             // 192
    const int tid = threadIdx.x;
    const int bk = blockIdx.x >> 6;
    const int b = bk >> 2, k = bk & 3;
    const int l0 = (blockIdx.x & 63) << 6;
    const float* seq = (k & 1) ? g_x1 : g_x0;

    for (int i = tid; i < 192 * 48; i += 256) wp_t[i] = 0.f;
    __syncthreads();

    for (int i = tid; i < 192 * 64; i += 256) {
        int d = i >> 6, c = i & 63;
        u_s[i] = seq[(size_t)(b * DIN + d) * LSEQ + l0 + c];
    }
    for (int i = tid; i < 38 * 192; i += 256) {
        int kk = i % 192, row = i / 192;
        wp_t[kk * 48 + row] = xpw[k * 38 * 192 + i];
    }
    for (int i = tid; i < 192 * 6;  i += 256) dw_s[i] = dtw[k * 192 * 6 + i];
    for (int i = tid; i < 192;      i += 256) db_s[i] = dtb[k * DIN + i];
    __syncthreads();

    const int col = tid & 63, grp = tid >> 6;
    u64 accp[6];
    #pragma unroll
    for (int j = 0; j < 6; j++) accp[j] = 0ull;
    #pragma unroll 2
    for (int kk = 0; kk < 192; kk++) {
        float uv = u_s[kk * 64 + col];
        u64 ud = dup2(uv);
        const ulonglong2* wp2 = (const ulonglong2*)(wp_t + kk * 48 + grp * 12);
        ulonglong2 wA = wp2[0], wB = wp2[1], wC = wp2[2];
        accp[0] = fma2(wA.x, ud, accp[0]);
        accp[1] = fma2(wA.y, ud, accp[1]);
        accp[2] = fma2(wB.x, ud, accp[2]);
        accp[3] = fma2(wB.y, ud, accp[3]);
        accp[4] = fma2(wC.x, ud, accp[4]);
        accp[5] = fma2(wC.y, ud, accp[5]);
    }
    #pragma unroll
    for (int j = 0; j < 6; j++) {
        float2 f = unp2(accp[j]);
        int row0 = grp * 12 + j * 2;
        if (row0 < 38)     xd_s[row0 * 65 + col] = f.x;
        if (row0 + 1 < 38) xd_s[(row0 + 1) * 65 + col] = f.y;
    }
    __syncthreads();

    const size_t lb4 = (size_t)bk * 1024 + (l0 >> 2);
    for (int i = tid; i < 16 * 64; i += 256) {
        int n = i & 15, cc = i >> 4;
        ((float*)g_bb4)[((lb4 + (cc >> 2)) * 16 + n) * 4 + (cc & 3)] = xd_s[(6 + n) * 65 + cc];
    }
    const size_t bcbase = (size_t)bk * LSEQ + l0;
    for (int i = tid; i < 8 * 64; i += 256) {
        int n8 = i & 7, cc = i >> 3;
        float4 v;
        v.x = xd_s[(6  + n8) * 65 + cc];
        v.y = xd_s[(22 + n8) * 65 + cc];
        v.z = xd_s[(14 + n8) * 65 + cc];
        v.w = xd_s[(30 + n8) * 65 + cc];
        g_bc4[(bcbase + cc) * 8 + n8] = v;
    }
    float xdv[6];
    #pragma unroll
    for (int r = 0; r < 6; r++) xdv[r] = xd_s[r * 65 + col];
    const int dg = tid >> 6;
    const size_t dbase = (size_t)bk * DIN * LSEQ;
    for (int j = 0; j < 48; j++) {
        int d = dg + 4 * j;
        float val = db_s[d];
        #pragma unroll
        for (int r = 0; r < 6; r++)
            val = fmaf(dw_s[d * 6 + r], xdv[r], val);
        val = fmaxf(val, 0.f) + log1pf(__expf(-fabsf(val)));
        g_delta[dbase + (size_t)d * LSEQ + l0 + col] = val;
    }
}

// ================= K4a: local chunk scan (smem-staged B, FIXED REV offsets) =====
template<bool REV>
__device__ __forceinline__ void k4a_body(const int K0, const float* __restrict__ alog,
                                         float4* sB)
{
    const int tid = threadIdx.x;
    const int lane = tid & 31, wi = tid >> 5;
    int bx = blockIdx.x;
    const int pb = bx % 12; bx /= 12;
    const int chunk = bx & 15; bx >>= 4;
    const int kk = bx & 1;
    const int b  = bx >> 1;
    const int p = pb * 8 + wi;
    const int half = lane >> 4, n = lane & 15;
    const int d = p * 2 + half;
    const int k = K0 + kk;
    const int bk = b * 4 + k;
    const int ch = bk * DIN + d;
    const float An2 = -__expf(alog[(k * DIN + d) * NST + n]) * 1.44269504f;

    // stage the CORRECT B tile: FWD -> [chunk*64, +64); REV -> [1024-(chunk+1)*64, +64)
    {
        const int tb = REV ? (1024 - (chunk + 1) * 64) : chunk * 64;
        const float4* src = g_bb4 + ((size_t)bk * 1024 + tb) * 16;
        #pragma unroll
        for (int i = 0; i < 4; i++) sB[tid + i * 256] = src[tid + i * 256];
    }
    __syncthreads();

    const float* dptr = g_delta + ((size_t)bk * DIN + d) * LSEQ;
    const float* uptr = (kk ? g_x1 : g_x0) + ((size_t)b * DIN + d) * LSEQ;

    float h = 0.f, sdel = 0.f;
    if (!REV) {
        const int i0 = chunk * CLEN;
        const float4* dp4 = (const float4*)(dptr + i0);
        const float4* up4 = (const float4*)(uptr + i0);
        #pragma unroll 2
        for (int s = 0; s < CLEN / 4; s++) {
            float4 d4 = dp4[s]; float4 u4 = up4[s];
            float4 b4 = sB[s * 16 + n];
            float dd[4] = {d4.x, d4.y, d4.z, d4.w};
            float uu[4] = {u4.x, u4.y, u4.z, u4.w};
            float bv[4] = {b4.x, b4.y, b4.z, b4.w};
            sdel += (dd[0] + dd[1]) + (dd[2] + dd[3]);
            #pragma unroll
            for (int j = 0; j < 4; j++) {
                float a = exp2f(dd[j] * An2);
                h = fmaf(a, h, dd[j] * uu[j] * bv[j]);
            }
        }
    } else {
        const int ltop = LSEQ - chunk * CLEN;
        const float4* dp4 = (const float4*)(dptr + ltop) - 1;
        const float4* up4 = (const float4*)(uptr + ltop) - 1;
        #pragma unroll 2
        for (int s = 0; s < CLEN / 4; s++) {
            float4 d4 = dp4[-s]; float4 u4 = up4[-s];
            float4 b4 = sB[(63 - s) * 16 + n];
            float dd[4] = {d4.x, d4.y, d4.z, d4.w};
            float uu[4] = {u4.x, u4.y, u4.z, u4.w};
            float bv[4] = {b4.x, b4.y, b4.z, b4.w};
            sdel += (dd[0] + dd[1]) + (dd[2] + dd[3]);
            #pragma unroll
            for (int j = 0; j < 4; j++) {
                const int e = 3 - j;
                float a = exp2f(dd[e] * An2);
                h = fmaf(a, h, dd[e] * uu[e] * bv[e]);
            }
        }
    }
    g_P [(ch * NCHUNK + chunk) * NST + n] = exp2f(An2 * sdel);
    g_he[(ch * NCHUNK + chunk) * NST + n] = h;
}

__global__ void __launch_bounds__(256, 6) k4a_scan(const float* __restrict__ alog)
{
    __shared__ float4 sB[1024];    // single 16KB allocation shared by both branches
    if (blockIdx.y == 0) k4a_body<false>(0, alog, sB);
    else                 k4a_body<true >(2, alog, sB);
}

// ================= K4b: carry across chunks =================
__global__ void k4b_carry()
{
    int idx = blockIdx.x * 256 + threadIdx.x;
    int ch = idx >> 4, n = idx & 15;
    float H = 0.f;
    #pragma unroll
    for (int c = 0; c < NCHUNK; c++) {
        int o = (ch * NCHUNK + c) * NST + n;
        g_H[o] = H;
        H = fmaf(g_P[o], H, g_he[o]);
    }
}

// ================= K4c: seeded scan, emit y (smem-staged BC, FIXED REV) =========
template<bool REV>
__device__ __forceinline__ void k4c_body(const int K0, const float* __restrict__ alog,
                                         const float* __restrict__ ds, float4* sBC)
{
    const int tid = threadIdx.x;
    const int lane = tid & 31, wi = tid >> 5;
    int bx = blockIdx.x;
    const int qb = bx % 6; bx /= 6;
    const int chunk = bx & 15; bx >>= 4;
    const int kk = bx & 1;
    const int b  = bx >> 1;
    const int q = qb * 8 + wi;
    const int c2 = lane >> 3;
    const int n0 = lane & 7;
    const int d = q * 4 + c2;
    const int k = K0 + kk;
    const int bk = b * 4 + k;
    const int ch = bk * DIN + d;

    // stage the CORRECT BC tile: FWD -> chunk*CLEN; REV -> LSEQ-(chunk+1)*CLEN
    {
        const int lt0 = REV ? (LSEQ - (chunk + 1) * CLEN) : chunk * CLEN;
        const float4* src = g_bc4 + ((size_t)bk * LSEQ + lt0) * 8;
        #pragma unroll
        for (int i = 0; i < 8; i++) sBC[tid + i * 256] = src[tid + i * 256];
    }
    __syncthreads();

    const float An0 = -__expf(alog[(k * DIN + d) * NST + n0]) * 1.44269504f;
    const float An1 = -__expf(alog[(k * DIN + d) * NST + n0 + 8]) * 1.44269504f;
    const float Dd = ds[k * DIN + d];

    const float* dptr = g_delta + ((size_t)bk * DIN + d) * LSEQ;
    const float* uptr = (kk ? g_x1 : g_x0) + ((size_t)b * DIN + d) * LSEQ;
    float* yp = g_y + ((size_t)(k * BATCH + b) * DIN + d) * LSEQ;

    float h0 = g_H[(ch * NCHUNK + chunk) * NST + n0];
    float h1 = g_H[(ch * NCHUNK + chunk) * NST + n0 + 8];

    if (!REV) {
        const int i0 = chunk * CLEN;
        const float4* dp4 = (const float4*)(dptr + i0);
        const float4* up4 = (const float4*)(uptr + i0);
        float4* yp4 = (float4*)(yp + i0);
        #pragma unroll 2
        for (int s = 0; s < CLEN / 4; s++) {
            float4 dv = dp4[s]; float4 uv = up4[s];
            float dd[4] = {dv.x, dv.y, dv.z, dv.w};
            float uu[4] = {uv.x, uv.y, uv.z, uv.w};
            float tr[4];
            #pragma unroll
            for (int j = 0; j < 4; j++) {
                float4 bc = sBC[(s * 4 + j) * 8 + n0];
                float du = dd[j] * uu[j];
                float a0 = exp2f(dd[j] * An0);
                float a1 = exp2f(dd[j] * An1);
                h0 = fmaf(a0, h0, du * bc.x);
                h1 = fmaf(a1, h1, du * bc.z);
                float t = fmaf(h1, bc.w, h0 * bc.y);
                t += __shfl_xor_sync(0xffffffffu, t, 4);
                t += __shfl_xor_sync(0xffffffffu, t, 2);
                t += __shfl_xor_sync(0xffffffffu, t, 1);
                tr[j] = fmaf(Dd, uu[j], t);
            }
            if (n0 == 0) yp4[s] = make_float4(tr[0], tr[1], tr[2], tr[3]);
        }
    } else {
        const int ltop = LSEQ - chunk * CLEN;
        const float4* dp4 = (const float4*)(dptr + ltop) - 1;
        const float4* up4 = (const float4*)(uptr + ltop) - 1;
        float4* yp4 = (float4*)(yp + ltop) - 1;
        #pragma unroll 2
        for (int s = 0; s < CLEN / 4; s++) {
            float4 dv = dp4[-s]; float4 uv = up4[-s];
            float dd[4] = {dv.x, dv.y, dv.z, dv.w};
            float uu[4] = {uv.x, uv.y, uv.z, uv.w};
            float tr[4];
            #pragma unroll
            for (int j = 0; j < 4; j++) {
                const int e = 3 - j;
                float4 bc = sBC[(CLEN - 1 - (s * 4 + j)) * 8 + n0];
                float du = dd[e] * uu[e];
                float a0 = exp2f(dd[e] * An0);
                float a1 = exp2f(dd[e] * An1);
                h0 = fmaf(a0, h0, du * bc.x);
                h1 = fmaf(a1, h1, du * bc.z);
                float t = fmaf(h1, bc.w, h0 * bc.y);
                t += __shfl_xor_sync(0xffffffffu, t, 4);
                t += __shfl_xor_sync(0xffffffffu, t, 2);
                t += __shfl_xor_sync(0xffffffffu, t, 1);
                tr[e] = fmaf(Dd, uu[e], t);
            }
            if (n0 == 0) yp4[-s] = make_float4(tr[0], tr[1], tr[2], tr[3]);
        }
    }
}

__global__ void __launch_bounds__(256, 6) k4c_scan(const float* __restrict__ alog,
                                                   const float* __restrict__ ds)
{
    __shared__ float4 sBC[2048];   // single 32KB allocation shared by both branches
    if (blockIdx.y == 0) k4c_body<false>(0, alog, ds, sBC);
    else                 k4c_body<true >(2, alog, ds, sBC);
}

// ================= K4t: transpose wh planes + merge all 4 into g_ysum =========
__global__ void k4t_merge()
{
    __shared__ float s1[64 * 65];
    __shared__ float s3[64 * 65];
    const int tid = threadIdx.x;
    const int b = blockIdx.x / DIN;
    const int d = blockIdx.x % DIN;
    const float4* p0 = (const float4*)(g_y + ((size_t)(0 * BATCH + b) * DIN + d) * LSEQ);
    const float4* p1 = (const float4*)(g_y + ((size_t)(1 * BATCH + b) * DIN + d) * LSEQ);
    const float4* p2 = (const float4*)(g_y + ((size_t)(2 * BATCH + b) * DIN + d) * LSEQ);
    const float4* p3 = (const float4*)(g_y + ((size_t)(3 * BATCH + b) * DIN + d) * LSEQ);

    for (int t4 = tid; t4 < 1024; t4 += 256) {
        int i = t4 * 4;
        int w_ = i >> 6, h0 = i & 63;
        float4 v1 = p1[t4], v3 = p3[t4];
        s1[(h0 + 0) * 65 + w_] = v1.x; s1[(h0 + 1) * 65 + w_] = v1.y;
        s1[(h0 + 2) * 65 + w_] = v1.z; s1[(h0 + 3) * 65 + w_] = v1.w;
        s3[(h0 + 0) * 65 + w_] = v3.x; s3[(h0 + 1) * 65 + w_] = v3.y;
        s3[(h0 + 2) * 65 + w_] = v3.z; s3[(h0 + 3) * 65 + w_] = v3.w;
    }
    __syncthreads();

    float4* po = (float4*)(g_ysum + (size_t)(b * DIN + d) * LSEQ);
    for (int t4 = tid; t4 < 1024; t4 += 256) {
        int j = t4 * 4;
        int h = j >> 6, w0 = j & 63;
        float4 a = p0[t4], c = p2[t4];
        float4 r;
        r.x = a.x + c.x + s1[h * 65 + w0 + 0] + s3[h * 65 + w0 + 0];
        r.y = a.y + c.y + s1[h * 65 + w0 + 1] + s3[h * 65 + w0 + 1];
        r.z = a.z + c.z + s1[h * 65 + w0 + 2] + s3[h * 65 + w0 + 2];
        r.w = a.w + c.w + s1[h * 65 + w0 + 3] + s3[h * 65 + w0 + 3];
        po[t4] = r;
    }
}

// ================= K5: out-LN + gate + out_proj + residual (f32x2) =============
__global__ void k5_final(const float* __restrict__ onw, const float* __restrict__ onb,
                         const float* __restrict__ wout, float* __restrict__ out)
{
    extern __shared__ float sm[];
    float* yc = sm;                  // 192*36
    float* ws = sm + 192 * 36;       // 96*192
    const int tid = threadIdx.x, lane = tid & 31, warp = tid >> 5;
    const int b = blockIdx.x >> 7;
    const int l0 = (blockIdx.x & 127) << 5;

    for (int i = tid; i < 192 * 32; i += 256) {
        int d = i >> 5, p = i & 31;
        yc[d * 36 + p] = g_ysum[(size_t)(b * DIN + d) * LSEQ + l0 + p];
    }
    for (int i = tid; i < 96 * 192; i += 256) ws[i] = wout[i];
    __syncthreads();

    #pragma unroll
    for (int pp = 0; pp < 4; pp++) {
        const int p = warp * 4 + pp;
        float s = 0.f, s2 = 0.f, vv[6];
        #pragma unroll
        for (int j = 0; j < 6; j++) {
            float v = yc[(lane + 32 * j) * 36 + p];
            vv[j] = v; s += v; s2 += v * v;
        }
        #pragma unroll
        for (int o = 16; o > 0; o >>= 1) {
            s  += __shfl_xor_sync(0xffffffffu, s,  o);
            s2 += __shfl_xor_sync(0xffffffffu, s2, o);
        }
        float mu = s * (1.f / 192.f);
        float var = s2 * (1.f / 192.f) - mu * mu;
        float rstd = rsqrtf(var + 1e-5f);
        size_t zbase = ((size_t)(b * LSEQ + l0 + p)) * DIN;
        #pragma unroll
        for (int j = 0; j < 6; j++) {
            int dd = lane + 32 * j;
            float g = (vv[j] - mu) * rstd * onw[dd] + onb[dd];
            yc[dd * 36 + p] = g * g_zs[zbase + dd];
        }
    }
    __syncthreads();

    const int og = tid >> 3;
    const int pg = tid & 7;
    u64 accp[3][2];
    #pragma unroll
    for (int a = 0; a < 3; a++) { accp[a][0] = 0ull; accp[a][1] = 0ull; }

    #pragma unroll 4
    for (int dd = 0; dd < 192; dd++) {
        ulonglong2 g = *(const ulonglong2*)&yc[dd * 36 + pg * 4];
        #pragma unroll
        for (int oi = 0; oi < 3; oi++) {
            u64 wd = dup2(ws[(og * 3 + oi) * 192 + dd]);
            accp[oi][0] = fma2(wd, g.x, accp[oi][0]);
            accp[oi][1] = fma2(wd, g.y, accp[oi][1]);
        }
    }
    __syncthreads();

    float* buf = sm;                 // 32 x 100 staging
    #pragma unroll
    for (int oi = 0; oi < 3; oi++) {
        float2 f0 = unp2(accp[oi][0]);
        float2 f1 = unp2(accp[oi][1]);
        buf[(pg * 4 + 0) * 100 + og * 3 + oi] = f0.x;
        buf[(pg * 4 + 1) * 100 + og * 3 + oi] = f0.y;
        buf[(pg * 4 + 2) * 100 + og * 3 + oi] = f1.x;
        buf[(pg * 4 + 3) * 100 + og * 3 + oi] = f1.y;
    }
    __syncthreads();

    const float4* df4 = (const float4*)(g_diff + ((size_t)b * LSEQ + l0) * CDIM);
    float4* out4 = (float4*)(out + ((size_t)b * LSEQ + l0) * CDIM);
    for (int t = tid; t < 32 * 24; t += 256) {
        int p = t / 24, o4 = t % 24;
        float4 v = *(const float4*)&buf[p * 100 + o4 * 4];
        float4 dv = df4[p * 24 + o4];
        v.x += dv.x; v.y += dv.y; v.z += dv.z; v.w += dv.w;
        out4[p * 24 + o4] = v;
    }
}

// ================= launch =================
extern "C" void kernel_launch(void* const* d_in, const int* in_sizes, int n_in,
                              void* d_out, int out_size)
{
    const float* x     = (const float*)d_in[0];
    const float* y     = (const float*)d_in[1];
    const float* ln_w  = (const float*)d_in[2];
    const float* ln_b  = (const float*)d_in[3];
    const float* ipw   = (const float*)d_in[4];
    const float* cw    = (const float*)d_in[5];
    const float* cb    = (const float*)d_in[6];
    const float* xpw   = (const float*)d_in[7];
    const float* dtw   = (const float*)d_in[8];
    const float* dtb   = (const float*)d_in[9];
    const float* alog  = (const float*)d_in[10];
    const float* ds    = (const float*)d_in[11];
    const float* onw   = (const float*)d_in[12];
    const float* onb   = (const float*)d_in[13];
    const float* wout  = (const float*)d_in[14];
    float* out = (float*)d_out;

    const int smem1 = (96 * 64 + 96 * 128) * 4;
    const int smem3 = (192 * 64 + 192 * 48 + 38 * 65 + 192 * 6 + 192) * 4;
    const int smem5 = (192 * 36 + 96 * 192) * 4;
    cudaFuncSetAttribute(k1_prologue, cudaFuncAttributeMaxDynamicSharedMemorySize, smem1);
    cudaFuncSetAttribute(k3_xproj,   cudaFuncAttributeMaxDynamicSharedMemorySize, smem3);
    cudaFuncSetAttribute(k5_final,   cudaFuncAttributeMaxDynamicSharedMemorySize, smem5);

    k1_prologue<<<dim3(128, 3), 256, smem1>>>(x, y, ln_w, ln_b, ipw);
    k2_conv<<<BATCH * DIN, 256>>>(cw, cb);
    k3_xproj<<<BATCH * 4 * (LSEQ / 64), 256, smem3>>>(xpw, dtw, dtb);
    k4a_scan<<<dim3(768, 2), 256>>>(alog);
    k4b_carry<<<NCH * NST / 256, 256>>>();
    k4c_scan<<<dim3(384, 2), 256>>>(alog, ds);
    k4t_merge<<<BATCH * DIN, 256>>>();
    k5_final<<<BATCH * (LSEQ / 32), 256, smem5>>>(onw, onb, wout, out);
}

// round 11
// speedup vs baseline: 1.0212x; 1.0212x over previous
#include <cuda_runtime.h>
#include <math.h>

#define BATCH 2
#define CDIM  96
#define DIN   192
#define NST   16
#define LSEQ  4096
#define NPIX  (BATCH*LSEQ)
#define NCH   (BATCH*4*DIN)
#define NCHUNK 16
#define CLEN  (LSEQ/NCHUNK)     // 256

typedef unsigned long long u64;

// ---------------- persistent device scratch ----------------
__device__ float  g_diff [NPIX*CDIM];
__device__ float  g_zs   [NPIX*DIN];
__device__ float  g_xm   [BATCH*DIN*LSEQ];
__device__ float  g_x0   [BATCH*DIN*LSEQ];
__device__ float  g_x1   [BATCH*DIN*LSEQ];
__device__ float  g_delta[BATCH*4*DIN*LSEQ];
__device__ float4 g_bb4  [BATCH*4*(LSEQ/4)*16];
__device__ float4 g_bc4  [BATCH*4*LSEQ*8];
__device__ float  g_y    [4*BATCH*DIN*LSEQ];
__device__ float  g_ysum [BATCH*DIN*LSEQ];
__device__ float  g_P    [NCH*NCHUNK*NST];
__device__ float  g_he   [NCH*NCHUNK*NST];
__device__ float  g_H    [NCH*NCHUNK*NST];

// ---- fast intrinsics (explicit MUFU, independent of -use_fast_math) ----
__device__ __forceinline__ float ex2(float x){ float r; asm("ex2.approx.f32 %0, %1;" : "=f"(r) : "f"(x)); return r; }
__device__ __forceinline__ float lg2(float x){ float r; asm("lg2.approx.f32 %0, %1;" : "=f"(r) : "f"(x)); return r; }
__device__ __forceinline__ float fexp(float x){ return ex2(x * 1.44269504f); }
__device__ __forceinline__ float silu_f(float v){ return v / (1.f + fexp(-v)); }

// ---- packed fp32x2 helpers (sm_103a) ----
__device__ __forceinline__ u64 dup2(float v) {
    u64 r; asm("mov.b64 %0, {%1, %1};" : "=l"(r) : "f"(v)); return r;
}
__device__ __forceinline__ u64 fma2(u64 a, u64 b, u64 c) {
    u64 d; asm("fma.rn.f32x2 %0, %1, %2, %3;" : "=l"(d) : "l"(a), "l"(b), "l"(c)); return d;
}
__device__ __forceinline__ u64 mul2(u64 a, u64 b) {
    u64 d; asm("mul.rn.f32x2 %0, %1, %2;" : "=l"(d) : "l"(a), "l"(b)); return d;
}
__device__ __forceinline__ u64 add2(u64 a, u64 b) {
    u64 d; asm("add.rn.f32x2 %0, %1, %2;" : "=l"(d) : "l"(a), "l"(b)); return d;
}
__device__ __forceinline__ float2 unp2(u64 v) {
    float2 r; asm("mov.b64 {%0, %1}, %2;" : "=f"(r.x), "=f"(r.y) : "l"(v)); return r;
}

// ================= K1: diff + LN + in_proj GEMM (f32x2) =================
__global__ void k1_prologue(const float* __restrict__ x, const float* __restrict__ y,
                            const float* __restrict__ lnw, const float* __restrict__ lnb,
                            const float* __restrict__ wproj)
{
    extern __shared__ float sm[];
    float* A_s = sm;            // 96*64
    float* W_s = sm + 96*64;    // 96*128
    const int tid = threadIdx.x, lane = tid & 31, warp = tid >> 5;
    const int pix0 = blockIdx.x * 64;
    const int oc = blockIdx.y;

    for (int pp = 0; pp < 8; pp++) {
        const int p = warp * 8 + pp;
        const int base = (pix0 + p) * CDIM;
        float vv[3]; float s = 0.f, s2 = 0.f;
        #pragma unroll
        for (int j = 0; j < 3; j++) {
            int ch = lane + 32 * j;
            float d = fabsf(x[base + ch] - y[base + ch]);
            if (oc == 0) g_diff[base + ch] = d;
            vv[j] = d; s += d; s2 += d * d;
        }
        #pragma unroll
        for (int o = 16; o > 0; o >>= 1) {
            s  += __shfl_xor_sync(0xffffffffu, s,  o);
            s2 += __shfl_xor_sync(0xffffffffu, s2, o);
        }
        float mu = s * (1.f / 96.f);
        float var = s2 * (1.f / 96.f) - mu * mu;
        float rstd = rsqrtf(var + 1e-5f);
        #pragma unroll
        for (int j = 0; j < 3; j++) {
            int ch = lane + 32 * j;
            A_s[ch * 64 + p] = (vv[j] - mu) * rstd * lnw[ch] + lnb[ch];
        }
    }
    for (int i = tid; i < 96 * 128; i += 256) {
        int kk = i % 96, j = i / 96;
        W_s[kk * 128 + j] = wproj[(oc * 128 + j) * 96 + kk];
    }
    __syncthreads();

    const int pg = tid & 7;
    const int og = tid >> 3;
    const float4* W4 = (const float4*)W_s;

    u64 accp[4][4];
    #pragma unroll
    for (int a = 0; a < 4; a++)
        #pragma unroll
        for (int b = 0; b < 4; b++) accp[a][b] = 0ull;

    #pragma unroll 4
    for (int kk = 0; kk < 96; kk++) {
        const ulonglong2* ap = (const ulonglong2*)(A_s + kk * 64 + pg * 8);
        ulonglong2 a01 = ap[0], a23 = ap[1];
        float4 w = W4[kk * 32 + og];
        u64 wd[4] = {dup2(w.x), dup2(w.y), dup2(w.z), dup2(w.w)};
        #pragma unroll
        for (int jj = 0; jj < 4; jj++) {
            accp[jj][0] = fma2(wd[jj], a01.x, accp[jj][0]);
            accp[jj][1] = fma2(wd[jj], a01.y, accp[jj][1]);
            accp[jj][2] = fma2(wd[jj], a23.x, accp[jj][2]);
            accp[jj][3] = fma2(wd[jj], a23.y, accp[jj][3]);
        }
    }

    float acc[4][8];
    #pragma unroll
    for (int jj = 0; jj < 4; jj++) {
        #pragma unroll
        for (int pr = 0; pr < 4; pr++) {
            float2 f = unp2(accp[jj][pr]);
            acc[jj][pr * 2] = f.x; acc[jj][pr * 2 + 1] = f.y;
        }
    }

    const int jg0 = oc * 128 + og * 4;
    const int pixb = pix0 + pg * 8;
    const int bb = pixb >> 12, lb = pixb & 4095;
    if (jg0 + 3 < DIN) {
        #pragma unroll
        for (int jj = 0; jj < 4; jj++) {
            float* row = g_xm + (size_t)(bb * DIN + jg0 + jj) * LSEQ + lb;
            *(float4*)row       = make_float4(acc[jj][0], acc[jj][1], acc[jj][2], acc[jj][3]);
            *(float4*)(row + 4) = make_float4(acc[jj][4], acc[jj][5], acc[jj][6], acc[jj][7]);
        }
    } else {
        const int zc = jg0 - DIN;
        #pragma unroll
        for (int pi = 0; pi < 8; pi++) {
            float* zp = g_zs + (size_t)(pixb + pi) * DIN + zc;
            *(float4*)zp = make_float4(silu_f(acc[0][pi]), silu_f(acc[1][pi]),
                                       silu_f(acc[2][pi]), silu_f(acc[3][pi]));
        }
    }
}

// ================= K2: depthwise conv + silu =================
__global__ void k2_conv(const float* __restrict__ cw, const float* __restrict__ cb)
{
    __shared__ float tin [64 * 65];
    __shared__ float tout[64 * 65];
    const int tid = threadIdx.x;
    const int bd = blockIdx.x;
    const int d = bd % DIN;
    const float* src = g_xm + (size_t)bd * LSEQ;

    for (int t = tid; t < 1024; t += 256) {
        float4 v = ((const float4*)src)[t];
        int i = t * 4;
        int h = i >> 6, w = i & 63;
        float* p = &tin[h * 65 + w];
        p[0] = v.x; p[1] = v.y; p[2] = v.z; p[3] = v.w;
    }
    float wreg[9];
    #pragma unroll
    for (int i = 0; i < 9; i++) wreg[i] = cw[d * 9 + i];
    const float bias = cb[d];
    __syncthreads();

    float* dst0 = g_x0 + (size_t)bd * LSEQ;
    for (int t = tid; t < 4096; t += 256) {
        int h = t >> 6, w = t & 63;
        float acc = bias;
        #pragma unroll
        for (int dy = 0; dy < 3; dy++) {
            int hh = h + dy - 1;
            if (hh < 0 || hh > 63) continue;
            #pragma unroll
            for (int dx = 0; dx < 3; dx++) {
                int ww = w + dx - 1;
                if (ww < 0 || ww > 63) continue;
                acc = fmaf(tin[hh * 65 + ww], wreg[dy * 3 + dx], acc);
            }
        }
        float v = silu_f(acc);
        dst0[t] = v;
        tout[h * 65 + w] = v;
    }
    __syncthreads();

    float* dst1 = g_x1 + (size_t)bd * LSEQ;
    for (int t = tid; t < 4096; t += 256) {
        int w = t >> 6, h = t & 63;
        dst1[t] = tout[h * 65 + w];
    }
}

// ================= K3: x_proj + dt_proj + softplus (f32x2, fast softplus) ======
__global__ void k3_xproj(const float* __restrict__ xpw, const float* __restrict__ dtw,
                         const float* __restrict__ dtb)
{
    extern __shared__ float sm[];
    float* u_s  = sm;                         // 192*64
    float* wp_t = u_s + 192 * 64;             // 192*48
    float* xd_s = wp_t + 192 * 48;            // 38*65
    float* dw_s = xd_s + 38 * 65;             // 192*6
    float* db_s = dw_s + 192 * 6;             // 192
    const int tid = threadIdx.x;
    const int bk = blockIdx.x >> 6;
    const int b = bk >> 2, k = bk & 3;
    const int l0 = (blockIdx.x & 63) << 6;
    const float* seq = (k & 1) ? g_x1 : g_x0;

    for (int i = tid; i < 192 * 48; i += 256) wp_t[i] = 0.f;
    __syncthreads();

    for (int i = tid; i < 192 * 64; i += 256) {
        int d = i >> 6, c = i & 63;
        u_s[i] = seq[(size_t)(b * DIN + d) * LSEQ + l0 + c];
    }
    for (int i = tid; i < 38 * 192; i += 256) {
        int kk = i % 192, row = i / 192;
        wp_t[kk * 48 + row] = xpw[k * 38 * 192 + i];
    }
    for (int i = tid; i < 192 * 6;  i += 256) dw_s[i] = dtw[k * 192 * 6 + i];
    for (int i = tid; i < 192;      i += 256) db_s[i] = dtb[k * DIN + i];
    __syncthreads();

    const int col = tid & 63, grp = tid >> 6;
    u64 accp[6];
    #pragma unroll
    for (int j = 0; j < 6; j++) accp[j] = 0ull;
    #pragma unroll 2
    for (int kk = 0; kk < 192; kk++) {
        float uv = u_s[kk * 64 + col];
        u64 ud = dup2(uv);
        const ulonglong2* wp2 = (const ulonglong2*)(wp_t + kk * 48 + grp * 12);
        ulonglong2 wA = wp2[0], wB = wp2[1], wC = wp2[2];
        accp[0] = fma2(wA.x, ud, accp[0]);
        accp[1] = fma2(wA.y, ud, accp[1]);
        accp[2] = fma2(wB.x, ud, accp[2]);
        accp[3] = fma2(wB.y, ud, accp[3]);
        accp[4] = fma2(wC.x, ud, accp[4]);
        accp[5] = fma2(wC.y, ud, accp[5]);
    }
    #pragma unroll
    for (int j = 0; j < 6; j++) {
        float2 f = unp2(accp[j]);
        int row0 = grp * 12 + j * 2;
        if (row0 < 38)     xd_s[row0 * 65 + col] = f.x;
        if (row0 + 1 < 38) xd_s[(row0 + 1) * 65 + col] = f.y;
    }
    __syncthreads();

    const size_t lb4 = (size_t)bk * 1024 + (l0 >> 2);
    for (int i = tid; i < 16 * 64; i += 256) {
        int n = i & 15, cc = i >> 4;
        ((float*)g_bb4)[((lb4 + (cc >> 2)) * 16 + n) * 4 + (cc & 3)] = xd_s[(6 + n) * 65 + cc];
    }
    const size_t bcbase = (size_t)bk * LSEQ + l0;
    for (int i = tid; i < 8 * 64; i += 256) {
        int n8 = i & 7, cc = i >> 3;
        float4 v;
        v.x = xd_s[(6  + n8) * 65 + cc];
        v.y = xd_s[(22 + n8) * 65 + cc];
        v.z = xd_s[(14 + n8) * 65 + cc];
        v.w = xd_s[(30 + n8) * 65 + cc];
        g_bc4[(bcbase + cc) * 8 + n8] = v;
    }
    float xdv[6];
    #pragma unroll
    for (int r = 0; r < 6; r++) xdv[r] = xd_s[r * 65 + col];
    const int dg = tid >> 6;
    const size_t dbase = (size_t)bk * DIN * LSEQ;
    for (int j = 0; j < 48; j++) {
        int d = dg + 4 * j;
        float val = db_s[d];
        #pragma unroll
        for (int r = 0; r < 6; r++)
            val = fmaf(dw_s[d * 6 + r], xdv[r], val);
        // softplus(x) = max(x,0) + log(1 + exp(-|x|))  via MUFU ex2/lg2
        float t = fexp(-fabsf(val));
        val = fmaxf(val, 0.f) + lg2(1.f + t) * 0.69314718f;
        g_delta[dbase + (size_t)d * LSEQ + l0 + col] = val;
    }
}

// ================= K4a: local chunk scan (smem-staged B, MUFU ex2, f32x2) ======
template<bool REV>
__device__ __forceinline__ void k4a_body(const int K0, const float* __restrict__ alog,
                                         float4* sB)
{
    const int tid = threadIdx.x;
    const int lane = tid & 31, wi = tid >> 5;
    int bx = blockIdx.x;
    const int pb = bx % 12; bx /= 12;
    const int chunk = bx & 15; bx >>= 4;
    const int kk = bx & 1;
    const int b  = bx >> 1;
    const int p = pb * 8 + wi;
    const int half = lane >> 4, n = lane & 15;
    const int d = p * 2 + half;
    const int k = K0 + kk;
    const int bk = b * 4 + k;
    const int ch = bk * DIN + d;
    const float An2 = -fexp(alog[(k * DIN + d) * NST + n]) * 1.44269504f;
    const u64 An2d = dup2(An2);

    {
        const int tb = REV ? (1024 - (chunk + 1) * 64) : chunk * 64;
        const float4* src = g_bb4 + ((size_t)bk * 1024 + tb) * 16;
        #pragma unroll
        for (int i = 0; i < 4; i++) sB[tid + i * 256] = src[tid + i * 256];
    }
    __syncthreads();

    const float* dptr = g_delta + ((size_t)bk * DIN + d) * LSEQ;
    const float* uptr = (kk ? g_x1 : g_x0) + ((size_t)b * DIN + d) * LSEQ;

    float h = 0.f;
    u64 sdel2 = 0ull;
    if (!REV) {
        const int i0 = chunk * CLEN;
        const ulonglong2* dp2 = (const ulonglong2*)(dptr + i0);
        const ulonglong2* up2 = (const ulonglong2*)(uptr + i0);
        #pragma unroll 4
        for (int s = 0; s < CLEN / 4; s++) {
            ulonglong2 dp = dp2[s], up = up2[s];
            float4 b4 = sB[s * 16 + n];
            u64 e01  = mul2(dp.x, An2d), e23  = mul2(dp.y, An2d);
            u64 du01 = mul2(dp.x, up.x), du23 = mul2(dp.y, up.y);
            sdel2 = add2(sdel2, dp.x); sdel2 = add2(sdel2, dp.y);
            float2 e0 = unp2(e01), e2 = unp2(e23);
            float2 dA = unp2(du01), dB = unp2(du23);
            h = fmaf(ex2(e0.x), h, dA.x * b4.x);
            h = fmaf(ex2(e0.y), h, dA.y * b4.y);
            h = fmaf(ex2(e2.x), h, dB.x * b4.z);
            h = fmaf(ex2(e2.y), h, dB.y * b4.w);
        }
    } else {
        const int ltop = LSEQ - chunk * CLEN;
        const ulonglong2* dp2 = (const ulonglong2*)(dptr + ltop) - 1;
        const ulonglong2* up2 = (const ulonglong2*)(uptr + ltop) - 1;
        #pragma unroll 4
        for (int s = 0; s < CLEN / 4; s++) {
            ulonglong2 dp = dp2[-s], up = up2[-s];
            float4 b4 = sB[(63 - s) * 16 + n];
            u64 e01  = mul2(dp.x, An2d), e23  = mul2(dp.y, An2d);
            u64 du01 = mul2(dp.x, up.x), du23 = mul2(dp.y, up.y);
            sdel2 = add2(sdel2, dp.x); sdel2 = add2(sdel2, dp.y);
            float2 e0 = unp2(e01), e2 = unp2(e23);
            float2 dA = unp2(du01), dB = unp2(du23);
            h = fmaf(ex2(e2.y), h, dB.y * b4.w);
            h = fmaf(ex2(e2.x), h, dB.x * b4.z);
            h = fmaf(ex2(e0.y), h, dA.y * b4.y);
            h = fmaf(ex2(e0.x), h, dA.x * b4.x);
        }
    }
    float2 sd = unp2(sdel2);
    g_P [(ch * NCHUNK + chunk) * NST + n] = ex2(An2 * (sd.x + sd.y));
    g_he[(ch * NCHUNK + chunk) * NST + n] = h;
}

__global__ void __launch_bounds__(256, 6) k4a_scan(const float* __restrict__ alog)
{
    __shared__ float4 sB[1024];
    if (blockIdx.y == 0) k4a_body<false>(0, alog, sB);
    else                 k4a_body<true >(2, alog, sB);
}

// ================= K4b: carry across chunks =================
__global__ void k4b_carry()
{
    int idx = blockIdx.x * 256 + threadIdx.x;
    int ch = idx >> 4, n = idx & 15;
    float H = 0.f;
    #pragma unroll
    for (int c = 0; c < NCHUNK; c++) {
        int o = (ch * NCHUNK + c) * NST + n;
        g_H[o] = H;
        H = fmaf(g_P[o], H, g_he[o]);
    }
}

// ================= K4c: seeded scan, emit y (smem BC, MUFU ex2, f32x2) =========
template<bool REV>
__device__ __forceinline__ void k4c_body(const int K0, const float* __restrict__ alog,
                                         const float* __restrict__ ds, float4* sBC)
{
    const int tid = threadIdx.x;
    const int lane = tid & 31, wi = tid >> 5;
    int bx = blockIdx.x;
    const int qb = bx % 6; bx /= 6;
    const int chunk = bx & 15; bx >>= 4;
    const int kk = bx & 1;
    const int b  = bx >> 1;
    const int q = qb * 8 + wi;
    const int c2 = lane >> 3;
    const int n0 = lane & 7;
    const int d = q * 4 + c2;
    const int k = K0 + kk;
    const int bk = b * 4 + k;
    const int ch = bk * DIN + d;

    {
        const int lt0 = REV ? (LSEQ - (chunk + 1) * CLEN) : chunk * CLEN;
        const float4* src = g_bc4 + ((size_t)bk * LSEQ + lt0) * 8;
        #pragma unroll
        for (int i = 0; i < 8; i++) sBC[tid + i * 256] = src[tid + i * 256];
    }
    __syncthreads();

    const float An0 = -fexp(alog[(k * DIN + d) * NST + n0]) * 1.44269504f;
    const float An1 = -fexp(alog[(k * DIN + d) * NST + n0 + 8]) * 1.44269504f;
    const u64 An0d = dup2(An0), An1d = dup2(An1);
    const float Dd = ds[k * DIN + d];
    const u64 Ddd = dup2(Dd);

    const float* dptr = g_delta + ((size_t)bk * DIN + d) * LSEQ;
    const float* uptr = (kk ? g_x1 : g_x0) + ((size_t)b * DIN + d) * LSEQ;
    float* yp = g_y + ((size_t)(k * BATCH + b) * DIN + d) * LSEQ;

    float h0 = g_H[(ch * NCHUNK + chunk) * NST + n0];
    float h1 = g_H[(ch * NCHUNK + chunk) * NST + n0 + 8];

    if (!REV) {
        const int i0 = chunk * CLEN;
        const ulonglong2* dp2 = (const ulonglong2*)(dptr + i0);
        const ulonglong2* up2 = (const ulonglong2*)(uptr + i0);
        float4* yp4 = (float4*)(yp + i0);
        #pragma unroll 2
        for (int s = 0; s < CLEN / 4; s++) {
            ulonglong2 dp = dp2[s], up = up2[s];
            u64 eA01 = mul2(dp.x, An0d), eA23 = mul2(dp.y, An0d);
            u64 eB01 = mul2(dp.x, An1d), eB23 = mul2(dp.y, An1d);
            u64 du01 = mul2(dp.x, up.x), du23 = mul2(dp.y, up.y);
            u64 gu01 = mul2(up.x, Ddd),  gu23 = mul2(up.y, Ddd);
            float2 eA0 = unp2(eA01), eA2 = unp2(eA23);
            float2 eB0 = unp2(eB01), eB2 = unp2(eB23);
            float2 duA = unp2(du01), duB = unp2(du23);
            float2 guA = unp2(gu01), guB = unp2(gu23);
            float eAj[4] = {eA0.x, eA0.y, eA2.x, eA2.y};
            float eBj[4] = {eB0.x, eB0.y, eB2.x, eB2.y};
            float duj[4] = {duA.x, duA.y, duB.x, duB.y};
            float guj[4] = {guA.x, guA.y, guB.x, guB.y};
            float tr[4];
            #pragma unroll
            for (int j = 0; j < 4; j++) {
                float4 bc = sBC[(s * 4 + j) * 8 + n0];
                h0 = fmaf(ex2(eAj[j]), h0, duj[j] * bc.x);
                h1 = fmaf(ex2(eBj[j]), h1, duj[j] * bc.z);
                float t = fmaf(h1, bc.w, h0 * bc.y);
                t += __shfl_xor_sync(0xffffffffu, t, 4);
                t += __shfl_xor_sync(0xffffffffu, t, 2);
                t += __shfl_xor_sync(0xffffffffu, t, 1);
                tr[j] = guj[j] + t;
            }
            if (n0 == 0) yp4[s] = make_float4(tr[0], tr[1], tr[2], tr[3]);
        }
    } else {
        const int ltop = LSEQ - chunk * CLEN;
        const ulonglong2* dp2 = (const ulonglong2*)(dptr + ltop) - 1;
        const ulonglong2* up2 = (const ulonglong2*)(uptr + ltop) - 1;
        float4* yp4 = (float4*)(yp + ltop) - 1;
        #pragma unroll 2
        for (int s = 0; s < CLEN / 4; s++) {
            ulonglong2 dp = dp2[-s], up = up2[-s];
            u64 eA01 = mul2(dp.x, An0d), eA23 = mul2(dp.y, An0d);
            u64 eB01 = mul2(dp.x, An1d), eB23 = mul2(dp.y, An1d);
            u64 du01 = mul2(dp.x, up.x), du23 = mul2(dp.y, up.y);
            u64 gu01 = mul2(up.x, Ddd),  gu23 = mul2(up.y, Ddd);
            float2 eA0 = unp2(eA01), eA2 = unp2(eA23);
            float2 eB0 = unp2(eB01), eB2 = unp2(eB23);
            float2 duA = unp2(du01), duB = unp2(du23);
            float2 guA = unp2(gu01), guB = unp2(gu23);
            float eAj[4] = {eA0.x, eA0.y, eA2.x, eA2.y};
            float eBj[4] = {eB0.x, eB0.y, eB2.x, eB2.y};
            float duj[4] = {duA.x, duA.y, duB.x, duB.y};
            float guj[4] = {guA.x, guA.y, guB.x, guB.y};
            float tr[4];
            #pragma unroll
            for (int j = 3; j >= 0; j--) {
                float4 bc = sBC[(CLEN - 1 - (s * 4 + (3 - j))) * 8 + n0];
                h0 = fmaf(ex2(eAj[j]), h0, duj[j] * bc.x);
                h1 = fmaf(ex2(eBj[j]), h1, duj[j] * bc.z);
                float t = fmaf(h1, bc.w, h0 * bc.y);
                t += __shfl_xor_sync(0xffffffffu, t, 4);
                t += __shfl_xor_sync(0xffffffffu, t, 2);
                t += __shfl_xor_sync(0xffffffffu, t, 1);
                tr[j] = guj[j] + t;
            }
            if (n0 == 0) yp4[-s] = make_float4(tr[0], tr[1], tr[2], tr[3]);
        }
    }
}

__global__ void __launch_bounds__(256, 6) k4c_scan(const float* __restrict__ alog,
                                                   const float* __restrict__ ds)
{
    __shared__ float4 sBC[2048];
    if (blockIdx.y == 0) k4c_body<false>(0, alog, ds, sBC);
    else                 k4c_body<true >(2, alog, ds, sBC);
}

// ================= K4t: transpose wh planes + merge all 4 into g_ysum =========
__global__ void k4t_merge()
{
    __shared__ float s1[64 * 65];
    __shared__ float s3[64 * 65];
    const int tid = threadIdx.x;
    const int b = blockIdx.x / DIN;
    const int d = blockIdx.x % DIN;
    const float4* p0 = (const float4*)(g_y + ((size_t)(0 * BATCH + b) * DIN + d) * LSEQ);
    const float4* p1 = (const float4*)(g_y + ((size_t)(1 * BATCH + b) * DIN + d) * LSEQ);
    const float4* p2 = (const float4*)(g_y + ((size_t)(2 * BATCH + b) * DIN + d) * LSEQ);
    const float4* p3 = (const float4*)(g_y + ((size_t)(3 * BATCH + b) * DIN + d) * LSEQ);

    for (int t4 = tid; t4 < 1024; t4 += 256) {
        int i = t4 * 4;
        int w_ = i >> 6, h0 = i & 63;
        float4 v1 = p1[t4], v3 = p3[t4];
        s1[(h0 + 0) * 65 + w_] = v1.x; s1[(h0 + 1) * 65 + w_] = v1.y;
        s1[(h0 + 2) * 65 + w_] = v1.z; s1[(h0 + 3) * 65 + w_] = v1.w;
        s3[(h0 + 0) * 65 + w_] = v3.x; s3[(h0 + 1) * 65 + w_] = v3.y;
        s3[(h0 + 2) * 65 + w_] = v3.z; s3[(h0 + 3) * 65 + w_] = v3.w;
    }
    __syncthreads();

    float4* po = (float4*)(g_ysum + (size_t)(b * DIN + d) * LSEQ);
    for (int t4 = tid; t4 < 1024; t4 += 256) {
        int j = t4 * 4;
        int h = j >> 6, w0 = j & 63;
        float4 a = p0[t4], c = p2[t4];
        float4 r;
        r.x = a.x + c.x + s1[h * 65 + w0 + 0] + s3[h * 65 + w0 + 0];
        r.y = a.y + c.y + s1[h * 65 + w0 + 1] + s3[h * 65 + w0 + 1];
        r.z = a.z + c.z + s1[h * 65 + w0 + 2] + s3[h * 65 + w0 + 2];
        r.w = a.w + c.w + s1[h * 65 + w0 + 3] + s3[h * 65 + w0 + 3];
        po[t4] = r;
    }
}

// ================= K5: out-LN + gate + out_proj + residual (f32x2) =============
__global__ void k5_final(const float* __restrict__ onw, const float* __restrict__ onb,
                         const float* __restrict__ wout, float* __restrict__ out)
{
    extern __shared__ float sm[];
    float* yc = sm;                  // 192*36
    float* ws = sm + 192 * 36;       // 96*192
    const int tid = threadIdx.x, lane = tid & 31, warp = tid >> 5;
    const int b = blockIdx.x >> 7;
    const int l0 = (blockIdx.x & 127) << 5;

    for (int i = tid; i < 192 * 32; i += 256) {
        int d = i >> 5, p = i & 31;
        yc[d * 36 + p] = g_ysum[(size_t)(b * DIN + d) * LSEQ + l0 + p];
    }
    for (int i = tid; i < 96 * 192; i += 256) ws[i] = wout[i];
    __syncthreads();

    #pragma unroll
    for (int pp = 0; pp < 4; pp++) {
        const int p = warp * 4 + pp;
        float s = 0.f, s2 = 0.f, vv[6];
        #pragma unroll
        for (int j = 0; j < 6; j++) {
            float v = yc[(lane + 32 * j) * 36 + p];
            vv[j] = v; s += v; s2 += v * v;
        }
        #pragma unroll
        for (int o = 16; o > 0; o >>= 1) {
            s  += __shfl_xor_sync(0xffffffffu, s,  o);
            s2 += __shfl_xor_sync(0xffffffffu, s2, o);
        }
        float mu = s * (1.f / 192.f);
        float var = s2 * (1.f / 192.f) - mu * mu;
        float rstd = rsqrtf(var + 1e-5f);
        size_t zbase = ((size_t)(b * LSEQ + l0 + p)) * DIN;
        #pragma unroll
        for (int j = 0; j < 6; j++) {
            int dd = lane + 32 * j;
            float g = (vv[j] - mu) * rstd * onw[dd] + onb[dd];
            yc[dd * 36 + p] = g * g_zs[zbase + dd];
        }
    }
    __syncthreads();

    const int og = tid >> 3;
    const int pg = tid & 7;
    u64 accp[3][2];
    #pragma unroll
    for (int a = 0; a < 3; a++) { accp[a][0] = 0ull; accp[a][1] = 0ull; }

    #pragma unroll 4
    for (int dd = 0; dd < 192; dd++) {
        ulonglong2 g = *(const ulonglong2*)&yc[dd * 36 + pg * 4];
        #pragma unroll
        for (int oi = 0; oi < 3; oi++) {
            u64 wd = dup2(ws[(og * 3 + oi) * 192 + dd]);
            accp[oi][0] = fma2(wd, g.x, accp[oi][0]);
            accp[oi][1] = fma2(wd, g.y, accp[oi][1]);
        }
    }
    __syncthreads();

    float* buf = sm;                 // 32 x 100 staging
    #pragma unroll
    for (int oi = 0; oi < 3; oi++) {
        float2 f0 = unp2(accp[oi][0]);
        float2 f1 = unp2(accp[oi][1]);
        buf[(pg * 4 + 0) * 100 + og * 3 + oi] = f0.x;
        buf[(pg * 4 + 1) * 100 + og * 3 + oi] = f0.y;
        buf[(pg * 4 + 2) * 100 + og * 3 + oi] = f1.x;
        buf[(pg * 4 + 3) * 100 + og * 3 + oi] = f1.y;
    }
    __syncthreads();

    const float4* df4 = (const float4*)(g_diff + ((size_t)b * LSEQ + l0) * CDIM);
    float4* out4 = (float4*)(out + ((size_t)b * LSEQ + l0) * CDIM);
    for (int t = tid; t < 32 * 24; t += 256) {
        int p = t / 24, o4 = t % 24;
        float4 v = *(const float4*)&buf[p * 100 + o4 * 4];
        float4 dv = df4[p * 24 + o4];
        v.x += dv.x; v.y += dv.y; v.z += dv.z; v.w += dv.w;
        out4[p * 24 + o4] = v;
    }
}

// ================= launch =================
extern "C" void kernel_launch(void* const* d_in, const int* in_sizes, int n_in,
                              void* d_out, int out_size)
{
    const float* x     = (const float*)d_in[0];
    const float* y     = (const float*)d_in[1];
    const float* ln_w  = (const float*)d_in[2];
    const float* ln_b  = (const float*)d_in[3];
    const float* ipw   = (const float*)d_in[4];
    const float* cw    = (const float*)d_in[5];
    const float* cb    = (const float*)d_in[6];
    const float* xpw   = (const float*)d_in[7];
    const float* dtw   = (const float*)d_in[8];
    const float* dtb   = (const float*)d_in[9];
    const float* alog  = (const float*)d_in[10];
    const float* ds    = (const float*)d_in[11];
    const float* onw   = (const float*)d_in[12];
    const float* onb   = (const float*)d_in[13];
    const float* wout  = (const float*)d_in[14];
    float* out = (float*)d_out;

    const int smem1 = (96 * 64 + 96 * 128) * 4;
    const int smem3 = (192 * 64 + 192 * 48 + 38 * 65 + 192 * 6 + 192) * 4;
    const int smem5 = (192 * 36 + 96 * 192) * 4;
    cudaFuncSetAttribute(k1_prologue, cudaFuncAttributeMaxDynamicSharedMemorySize, smem1);
    cudaFuncSetAttribute(k3_xproj,   cudaFuncAttributeMaxDynamicSharedMemorySize, smem3);
    cudaFuncSetAttribute(k5_final,   cudaFuncAttributeMaxDynamicSharedMemorySize, smem5);

    k1_prologue<<<dim3(128, 3), 256, smem1>>>(x, y, ln_w, ln_b, ipw);
    k2_conv<<<BATCH * DIN, 256>>>(cw, cb);
    k3_xproj<<<BATCH * 4 * (LSEQ / 64), 256, smem3>>>(xpw, dtw, dtb);
    k4a_scan<<<dim3(768, 2), 256>>>(alog);
    k4b_carry<<<NCH * NST / 256, 256>>>();
    k4c_scan<<<dim3(384, 2), 256>>>(alog, ds);
    k4t_merge<<<BATCH * DIN, 256>>>();
    k5_final<<<BATCH * (LSEQ / 32), 256, smem5>>>(onw, onb, wout, out);
}

// round 12
// speedup vs baseline: 1.0456x; 1.0239x over previous
#include <cuda_runtime.h>
#include <math.h>

#define BATCH 2
#define CDIM  96
#define DIN   192
#define NST   16
#define LSEQ  4096
#define NPIX  (BATCH*LSEQ)
#define NCH   (BATCH*4*DIN)
#define NCHUNK 16
#define CLEN  (LSEQ/NCHUNK)     // 256

typedef unsigned long long u64;

// ---------------- persistent device scratch ----------------
__device__ float  g_diff [NPIX*CDIM];
__device__ float  g_zs   [NPIX*DIN];
__device__ float  g_xm   [BATCH*DIN*LSEQ];
__device__ float  g_x0   [BATCH*DIN*LSEQ];
__device__ float  g_x1   [BATCH*DIN*LSEQ];
__device__ float  g_delta[BATCH*4*DIN*LSEQ];
__device__ float4 g_bb4  [BATCH*4*(LSEQ/4)*16];
__device__ float4 g_bc4  [BATCH*4*LSEQ*8];
__device__ float  g_y    [4*BATCH*DIN*LSEQ];
__device__ float  g_ysum [BATCH*DIN*LSEQ];
__device__ float  g_P    [NCH*NCHUNK*NST];
__device__ float  g_he   [NCH*NCHUNK*NST];
__device__ float  g_H    [NCH*NCHUNK*NST];

// ---- fast intrinsics ----
__device__ __forceinline__ float ex2(float x){ float r; asm("ex2.approx.f32 %0, %1;" : "=f"(r) : "f"(x)); return r; }
__device__ __forceinline__ float lg2(float x){ float r; asm("lg2.approx.f32 %0, %1;" : "=f"(r) : "f"(x)); return r; }
__device__ __forceinline__ float fexp(float x){ return ex2(x * 1.44269504f); }
__device__ __forceinline__ float silu_f(float v){ return v / (1.f + fexp(-v)); }

// ---- packed fp32x2 helpers (sm_103a) ----
__device__ __forceinline__ u64 dup2(float v) {
    u64 r; asm("mov.b64 %0, {%1, %1};" : "=l"(r) : "f"(v)); return r;
}
__device__ __forceinline__ u64 fma2(u64 a, u64 b, u64 c) {
    u64 d; asm("fma.rn.f32x2 %0, %1, %2, %3;" : "=l"(d) : "l"(a), "l"(b), "l"(c)); return d;
}
__device__ __forceinline__ u64 mul2(u64 a, u64 b) {
    u64 d; asm("mul.rn.f32x2 %0, %1, %2;" : "=l"(d) : "l"(a), "l"(b)); return d;
}
__device__ __forceinline__ u64 add2(u64 a, u64 b) {
    u64 d; asm("add.rn.f32x2 %0, %1, %2;" : "=l"(d) : "l"(a), "l"(b)); return d;
}
__device__ __forceinline__ float2 unp2(u64 v) {
    float2 r; asm("mov.b64 {%0, %1}, %2;" : "=f"(r.x), "=f"(r.y) : "l"(v)); return r;
}

// ================= K1: diff + LN + in_proj GEMM (f32x2) =================
__global__ void k1_prologue(const float* __restrict__ x, const float* __restrict__ y,
                            const float* __restrict__ lnw, const float* __restrict__ lnb,
                            const float* __restrict__ wproj)
{
    extern __shared__ float sm[];
    float* A_s = sm;            // 96*64
    float* W_s = sm + 96*64;    // 96*128
    const int tid = threadIdx.x, lane = tid & 31, warp = tid >> 5;
    const int pix0 = blockIdx.x * 64;
    const int oc = blockIdx.y;

    for (int pp = 0; pp < 8; pp++) {
        const int p = warp * 8 + pp;
        const int base = (pix0 + p) * CDIM;
        float vv[3]; float s = 0.f, s2 = 0.f;
        #pragma unroll
        for (int j = 0; j < 3; j++) {
            int ch = lane + 32 * j;
            float d = fabsf(x[base + ch] - y[base + ch]);
            if (oc == 0) g_diff[base + ch] = d;
            vv[j] = d; s += d; s2 += d * d;
        }
        #pragma unroll
        for (int o = 16; o > 0; o >>= 1) {
            s  += __shfl_xor_sync(0xffffffffu, s,  o);
            s2 += __shfl_xor_sync(0xffffffffu, s2, o);
        }
        float mu = s * (1.f / 96.f);
        float var = s2 * (1.f / 96.f) - mu * mu;
        float rstd = rsqrtf(var + 1e-5f);
        #pragma unroll
        for (int j = 0; j < 3; j++) {
            int ch = lane + 32 * j;
            A_s[ch * 64 + p] = (vv[j] - mu) * rstd * lnw[ch] + lnb[ch];
        }
    }
    for (int i = tid; i < 96 * 128; i += 256) {
        int kk = i % 96, j = i / 96;
        W_s[kk * 128 + j] = wproj[(oc * 128 + j) * 96 + kk];
    }
    __syncthreads();

    const int pg = tid & 7;
    const int og = tid >> 3;
    const float4* W4 = (const float4*)W_s;

    u64 accp[4][4];
    #pragma unroll
    for (int a = 0; a < 4; a++)
        #pragma unroll
        for (int b = 0; b < 4; b++) accp[a][b] = 0ull;

    #pragma unroll 4
    for (int kk = 0; kk < 96; kk++) {
        const ulonglong2* ap = (const ulonglong2*)(A_s + kk * 64 + pg * 8);
        ulonglong2 a01 = ap[0], a23 = ap[1];
        float4 w = W4[kk * 32 + og];
        u64 wd[4] = {dup2(w.x), dup2(w.y), dup2(w.z), dup2(w.w)};
        #pragma unroll
        for (int jj = 0; jj < 4; jj++) {
            accp[jj][0] = fma2(wd[jj], a01.x, accp[jj][0]);
            accp[jj][1] = fma2(wd[jj], a01.y, accp[jj][1]);
            accp[jj][2] = fma2(wd[jj], a23.x, accp[jj][2]);
            accp[jj][3] = fma2(wd[jj], a23.y, accp[jj][3]);
        }
    }

    float acc[4][8];
    #pragma unroll
    for (int jj = 0; jj < 4; jj++) {
        #pragma unroll
        for (int pr = 0; pr < 4; pr++) {
            float2 f = unp2(accp[jj][pr]);
            acc[jj][pr * 2] = f.x; acc[jj][pr * 2 + 1] = f.y;
        }
    }

    const int jg0 = oc * 128 + og * 4;
    const int pixb = pix0 + pg * 8;
    const int bb = pixb >> 12, lb = pixb & 4095;
    if (jg0 + 3 < DIN) {
        #pragma unroll
        for (int jj = 0; jj < 4; jj++) {
            float* row = g_xm + (size_t)(bb * DIN + jg0 + jj) * LSEQ + lb;
            *(float4*)row       = make_float4(acc[jj][0], acc[jj][1], acc[jj][2], acc[jj][3]);
            *(float4*)(row + 4) = make_float4(acc[jj][4], acc[jj][5], acc[jj][6], acc[jj][7]);
        }
    } else {
        const int zc = jg0 - DIN;
        #pragma unroll
        for (int pi = 0; pi < 8; pi++) {
            float* zp = g_zs + (size_t)(pixb + pi) * DIN + zc;
            *(float4*)zp = make_float4(silu_f(acc[0][pi]), silu_f(acc[1][pi]),
                                       silu_f(acc[2][pi]), silu_f(acc[3][pi]));
        }
    }
}

// ================= K2: depthwise conv + silu =================
__global__ void k2_conv(const float* __restrict__ cw, const float* __restrict__ cb)
{
    __shared__ float tin [64 * 65];
    __shared__ float tout[64 * 65];
    const int tid = threadIdx.x;
    const int bd = blockIdx.x;
    const int d = bd % DIN;
    const float* src = g_xm + (size_t)bd * LSEQ;

    for (int t = tid; t < 1024; t += 256) {
        float4 v = ((const float4*)src)[t];
        int i = t * 4;
        int h = i >> 6, w = i & 63;
        float* p = &tin[h * 65 + w];
        p[0] = v.x; p[1] = v.y; p[2] = v.z; p[3] = v.w;
    }
    float wreg[9];
    #pragma unroll
    for (int i = 0; i < 9; i++) wreg[i] = cw[d * 9 + i];
    const float bias = cb[d];
    __syncthreads();

    float* dst0 = g_x0 + (size_t)bd * LSEQ;
    for (int t = tid; t < 4096; t += 256) {
        int h = t >> 6, w = t & 63;
        float acc = bias;
        #pragma unroll
        for (int dy = 0; dy < 3; dy++) {
            int hh = h + dy - 1;
            if (hh < 0 || hh > 63) continue;
            #pragma unroll
            for (int dx = 0; dx < 3; dx++) {
                int ww = w + dx - 1;
                if (ww < 0 || ww > 63) continue;
                acc = fmaf(tin[hh * 65 + ww], wreg[dy * 3 + dx], acc);
            }
        }
        float v = silu_f(acc);
        dst0[t] = v;
        tout[h * 65 + w] = v;
    }
    __syncthreads();

    float* dst1 = g_x1 + (size_t)bd * LSEQ;
    for (int t = tid; t < 4096; t += 256) {
        int w = t >> 6, h = t & 63;
        dst1[t] = tout[h * 65 + w];
    }
}

// ================= K3: x_proj + dt_proj + softplus (u via LDG, smaller smem) ====
__global__ void __launch_bounds__(256, 4) k3_xproj(const float* __restrict__ xpw,
                                                   const float* __restrict__ dtw,
                                                   const float* __restrict__ dtb)
{
    extern __shared__ float sm[];
    float* wp_t = sm;                         // 192*48
    float* xd_s = wp_t + 192 * 48;            // 38*65
    float* dw_s = xd_s + 38 * 65;             // 192*6
    float* db_s = dw_s + 192 * 6;             // 192
    const int tid = threadIdx.x;
    const int bk = blockIdx.x >> 6;
    const int b = bk >> 2, k = bk & 3;
    const int l0 = (blockIdx.x & 63) << 6;
    const float* seq = (k & 1) ? g_x1 : g_x0;

    for (int i = tid; i < 192 * 48; i += 256) wp_t[i] = 0.f;
    __syncthreads();

    for (int i = tid; i < 38 * 192; i += 256) {
        int kk = i % 192, row = i / 192;
        wp_t[kk * 48 + row] = xpw[k * 38 * 192 + i];
    }
    for (int i = tid; i < 192 * 6;  i += 256) dw_s[i] = dtw[k * 192 * 6 + i];
    for (int i = tid; i < 192;      i += 256) db_s[i] = dtb[k * DIN + i];
    __syncthreads();

    const int col = tid & 63, grp = tid >> 6;
    const float* up = seq + (size_t)b * DIN * LSEQ + l0 + col;
    u64 accp[6];
    #pragma unroll
    for (int j = 0; j < 6; j++) accp[j] = 0ull;
    #pragma unroll 2
    for (int kk = 0; kk < 192; kk++) {
        float uv = __ldg(up + (size_t)kk * LSEQ);
        u64 ud = dup2(uv);
        const ulonglong2* wp2 = (const ulonglong2*)(wp_t + kk * 48 + grp * 12);
        ulonglong2 wA = wp2[0], wB = wp2[1], wC = wp2[2];
        accp[0] = fma2(wA.x, ud, accp[0]);
        accp[1] = fma2(wA.y, ud, accp[1]);
        accp[2] = fma2(wB.x, ud, accp[2]);
        accp[3] = fma2(wB.y, ud, accp[3]);
        accp[4] = fma2(wC.x, ud, accp[4]);
        accp[5] = fma2(wC.y, ud, accp[5]);
    }
    #pragma unroll
    for (int j = 0; j < 6; j++) {
        float2 f = unp2(accp[j]);
        int row0 = grp * 12 + j * 2;
        if (row0 < 38)     xd_s[row0 * 65 + col] = f.x;
        if (row0 + 1 < 38) xd_s[(row0 + 1) * 65 + col] = f.y;
    }
    __syncthreads();

    const size_t lb4 = (size_t)bk * 1024 + (l0 >> 2);
    for (int i = tid; i < 16 * 64; i += 256) {
        int n = i & 15, cc = i >> 4;
        ((float*)g_bb4)[((lb4 + (cc >> 2)) * 16 + n) * 4 + (cc & 3)] = xd_s[(6 + n) * 65 + cc];
    }
    const size_t bcbase = (size_t)bk * LSEQ + l0;
    for (int i = tid; i < 8 * 64; i += 256) {
        int n8 = i & 7, cc = i >> 3;
        float4 v;
        v.x = xd_s[(6  + n8) * 65 + cc];
        v.y = xd_s[(22 + n8) * 65 + cc];
        v.z = xd_s[(14 + n8) * 65 + cc];
        v.w = xd_s[(30 + n8) * 65 + cc];
        g_bc4[(bcbase + cc) * 8 + n8] = v;
    }
    float xdv[6];
    #pragma unroll
    for (int r = 0; r < 6; r++) xdv[r] = xd_s[r * 65 + col];
    const int dg = tid >> 6;
    const size_t dbase = (size_t)bk * DIN * LSEQ;
    for (int j = 0; j < 48; j++) {
        int d = dg + 4 * j;
        float val = db_s[d];
        #pragma unroll
        for (int r = 0; r < 6; r++)
            val = fmaf(dw_s[d * 6 + r], xdv[r], val);
        float t = fexp(-fabsf(val));
        val = fmaxf(val, 0.f) + lg2(1.f + t) * 0.69314718f;
        g_delta[dbase + (size_t)d * LSEQ + l0 + col] = val;
    }
}

// ================= K4a: local chunk scan (smem-staged B, f32x2) ======
template<bool REV>
__device__ __forceinline__ void k4a_body(const int K0, const float* __restrict__ alog,
                                         float4* sB)
{
    const int tid = threadIdx.x;
    const int lane = tid & 31, wi = tid >> 5;
    int bx = blockIdx.x;
    const int pb = bx % 12; bx /= 12;
    const int chunk = bx & 15; bx >>= 4;
    const int kk = bx & 1;
    const int b  = bx >> 1;
    const int p = pb * 8 + wi;
    const int half = lane >> 4, n = lane & 15;
    const int d = p * 2 + half;
    const int k = K0 + kk;
    const int bk = b * 4 + k;
    const int ch = bk * DIN + d;
    const float An2 = -fexp(alog[(k * DIN + d) * NST + n]) * 1.44269504f;
    const u64 An2d = dup2(An2);

    {
        const int tb = REV ? (1024 - (chunk + 1) * 64) : chunk * 64;
        const float4* src = g_bb4 + ((size_t)bk * 1024 + tb) * 16;
        #pragma unroll
        for (int i = 0; i < 4; i++) sB[tid + i * 256] = src[tid + i * 256];
    }
    __syncthreads();

    const float* dptr = g_delta + ((size_t)bk * DIN + d) * LSEQ;
    const float* uptr = (kk ? g_x1 : g_x0) + ((size_t)b * DIN + d) * LSEQ;

    float h = 0.f;
    u64 sdel2 = 0ull;
    if (!REV) {
        const int i0 = chunk * CLEN;
        const ulonglong2* dp2 = (const ulonglong2*)(dptr + i0);
        const ulonglong2* up2 = (const ulonglong2*)(uptr + i0);
        #pragma unroll 4
        for (int s = 0; s < CLEN / 4; s++) {
            ulonglong2 dp = dp2[s], up = up2[s];
            float4 b4 = sB[s * 16 + n];
            u64 e01  = mul2(dp.x, An2d), e23  = mul2(dp.y, An2d);
            u64 du01 = mul2(dp.x, up.x), du23 = mul2(dp.y, up.y);
            sdel2 = add2(sdel2, dp.x); sdel2 = add2(sdel2, dp.y);
            float2 e0 = unp2(e01), e2 = unp2(e23);
            float2 dA = unp2(du01), dB = unp2(du23);
            h = fmaf(ex2(e0.x), h, dA.x * b4.x);
            h = fmaf(ex2(e0.y), h, dA.y * b4.y);
            h = fmaf(ex2(e2.x), h, dB.x * b4.z);
            h = fmaf(ex2(e2.y), h, dB.y * b4.w);
        }
    } else {
        const int ltop = LSEQ - chunk * CLEN;
        const ulonglong2* dp2 = (const ulonglong2*)(dptr + ltop) - 1;
        const ulonglong2* up2 = (const ulonglong2*)(uptr + ltop) - 1;
        #pragma unroll 4
        for (int s = 0; s < CLEN / 4; s++) {
            ulonglong2 dp = dp2[-s], up = up2[-s];
            float4 b4 = sB[(63 - s) * 16 + n];
            u64 e01  = mul2(dp.x, An2d), e23  = mul2(dp.y, An2d);
            u64 du01 = mul2(dp.x, up.x), du23 = mul2(dp.y, up.y);
            sdel2 = add2(sdel2, dp.x); sdel2 = add2(sdel2, dp.y);
            float2 e0 = unp2(e01), e2 = unp2(e23);
            float2 dA = unp2(du01), dB = unp2(du23);
            h = fmaf(ex2(e2.y), h, dB.y * b4.w);
            h = fmaf(ex2(e2.x), h, dB.x * b4.z);
            h = fmaf(ex2(e0.y), h, dA.y * b4.y);
            h = fmaf(ex2(e0.x), h, dA.x * b4.x);
        }
    }
    float2 sd = unp2(sdel2);
    g_P [(ch * NCHUNK + chunk) * NST + n] = ex2(An2 * (sd.x + sd.y));
    g_he[(ch * NCHUNK + chunk) * NST + n] = h;
}

__global__ void __launch_bounds__(256, 6) k4a_scan(const float* __restrict__ alog)
{
    __shared__ float4 sB[1024];
    if (blockIdx.y == 0) k4a_body<false>(0, alog, sB);
    else                 k4a_body<true >(2, alog, sB);
}

// ================= K4b: carry across chunks =================
__global__ void k4b_carry()
{
    int idx = blockIdx.x * 256 + threadIdx.x;
    int ch = idx >> 4, n = idx & 15;
    float H = 0.f;
    #pragma unroll
    for (int c = 0; c < NCHUNK; c++) {
        int o = (ch * NCHUNK + c) * NST + n;
        g_H[o] = H;
        H = fmaf(g_P[o], H, g_he[o]);
    }
}

// ================= K4c: seeded scan, emit y (smem BC, f32x2) =========
template<bool REV>
__device__ __forceinline__ void k4c_body(const int K0, const float* __restrict__ alog,
                                         const float* __restrict__ ds, float4* sBC)
{
    const int tid = threadIdx.x;
    const int lane = tid & 31, wi = tid >> 5;
    int bx = blockIdx.x;
    const int qb = bx % 6; bx /= 6;
    const int chunk = bx & 15; bx >>= 4;
    const int kk = bx & 1;
    const int b  = bx >> 1;
    const int q = qb * 8 + wi;
    const int c2 = lane >> 3;
    const int n0 = lane & 7;
    const int d = q * 4 + c2;
    const int k = K0 + kk;
    const int bk = b * 4 + k;
    const int ch = bk * DIN + d;

    {
        const int lt0 = REV ? (LSEQ - (chunk + 1) * CLEN) : chunk * CLEN;
        const float4* src = g_bc4 + ((size_t)bk * LSEQ + lt0) * 8;
        #pragma unroll
        for (int i = 0; i < 8; i++) sBC[tid + i * 256] = src[tid + i * 256];
    }
    __syncthreads();

    const float An0 = -fexp(alog[(k * DIN + d) * NST + n0]) * 1.44269504f;
    const float An1 = -fexp(alog[(k * DIN + d) * NST + n0 + 8]) * 1.44269504f;
    const u64 An0d = dup2(An0), An1d = dup2(An1);
    const float Dd = ds[k * DIN + d];
    const u64 Ddd = dup2(Dd);

    const float* dptr = g_delta + ((size_t)bk * DIN + d) * LSEQ;
    const float* uptr = (kk ? g_x1 : g_x0) + ((size_t)b * DIN + d) * LSEQ;
    float* yp = g_y + ((size_t)(k * BATCH + b) * DIN + d) * LSEQ;

    float h0 = g_H[(ch * NCHUNK + chunk) * NST + n0];
    float h1 = g_H[(ch * NCHUNK + chunk) * NST + n0 + 8];

    if (!REV) {
        const int i0 = chunk * CLEN;
        const ulonglong2* dp2 = (const ulonglong2*)(dptr + i0);
        const ulonglong2* up2 = (const ulonglong2*)(uptr + i0);
        float4* yp4 = (float4*)(yp + i0);
        #pragma unroll 2
        for (int s = 0; s < CLEN / 4; s++) {
            ulonglong2 dp = dp2[s], up = up2[s];
            u64 eA01 = mul2(dp.x, An0d), eA23 = mul2(dp.y, An0d);
            u64 eB01 = mul2(dp.x, An1d), eB23 = mul2(dp.y, An1d);
            u64 du01 = mul2(dp.x, up.x), du23 = mul2(dp.y, up.y);
            u64 gu01 = mul2(up.x, Ddd),  gu23 = mul2(up.y, Ddd);
            float2 eA0 = unp2(eA01), eA2 = unp2(eA23);
            float2 eB0 = unp2(eB01), eB2 = unp2(eB23);
            float2 duA = unp2(du01), duB = unp2(du23);
            float2 guA = unp2(gu01), guB = unp2(gu23);
            float eAj[4] = {eA0.x, eA0.y, eA2.x, eA2.y};
            float eBj[4] = {eB0.x, eB0.y, eB2.x, eB2.y};
            float duj[4] = {duA.x, duA.y, duB.x, duB.y};
            float guj[4] = {guA.x, guA.y, guB.x, guB.y};
            float tr[4];
            #pragma unroll
            for (int j = 0; j < 4; j++) {
                float4 bc = sBC[(s * 4 + j) * 8 + n0];
                h0 = fmaf(ex2(eAj[j]), h0, duj[j] * bc.x);
                h1 = fmaf(ex2(eBj[j]), h1, duj[j] * bc.z);
                float t = fmaf(h1, bc.w, h0 * bc.y);
                t += __shfl_xor_sync(0xffffffffu, t, 4);
                t += __shfl_xor_sync(0xffffffffu, t, 2);
                t += __shfl_xor_sync(0xffffffffu, t, 1);
                tr[j] = guj[j] + t;
            }
            if (n0 == 0) yp4[s] = make_float4(tr[0], tr[1], tr[2], tr[3]);
        }
    } else {
        const int ltop = LSEQ - chunk * CLEN;
        const ulonglong2* dp2 = (const ulonglong2*)(dptr + ltop) - 1;
        const ulonglong2* up2 = (const ulonglong2*)(uptr + ltop) - 1;
        float4* yp4 = (float4*)(yp + ltop) - 1;
        #pragma unroll 2
        for (int s = 0; s < CLEN / 4; s++) {
            ulonglong2 dp = dp2[-s], up = up2[-s];
            u64 eA01 = mul2(dp.x, An0d), eA23 = mul2(dp.y, An0d);
            u64 eB01 = mul2(dp.x, An1d), eB23 = mul2(dp.y, An1d);
            u64 du01 = mul2(dp.x, up.x), du23 = mul2(dp.y, up.y);
            u64 gu01 = mul2(up.x, Ddd),  gu23 = mul2(up.y, Ddd);
            float2 eA0 = unp2(eA01), eA2 = unp2(eA23);
            float2 eB0 = unp2(eB01), eB2 = unp2(eB23);
            float2 duA = unp2(du01), duB = unp2(du23);
            float2 guA = unp2(gu01), guB = unp2(gu23);
            float eAj[4] = {eA0.x, eA0.y, eA2.x, eA2.y};
            float eBj[4] = {eB0.x, eB0.y, eB2.x, eB2.y};
            float duj[4] = {duA.x, duA.y, duB.x, duB.y};
            float guj[4] = {guA.x, guA.y, guB.x, guB.y};
            float tr[4];
            #pragma unroll
            for (int j = 3; j >= 0; j--) {
                float4 bc = sBC[(CLEN - 1 - (s * 4 + (3 - j))) * 8 + n0];
                h0 = fmaf(ex2(eAj[j]), h0, duj[j] * bc.x);
                h1 = fmaf(ex2(eBj[j]), h1, duj[j] * bc.z);
                float t = fmaf(h1, bc.w, h0 * bc.y);
                t += __shfl_xor_sync(0xffffffffu, t, 4);
                t += __shfl_xor_sync(0xffffffffu, t, 2);
                t += __shfl_xor_sync(0xffffffffu, t, 1);
                tr[j] = guj[j] + t;
            }
            if (n0 == 0) yp4[-s] = make_float4(tr[0], tr[1], tr[2], tr[3]);
        }
    }
}

__global__ void __launch_bounds__(256, 6) k4c_scan(const float* __restrict__ alog,
                                                   const float* __restrict__ ds)
{
    __shared__ float4 sBC[2048];
    if (blockIdx.y == 0) k4c_body<false>(0, alog, ds, sBC);
    else                 k4c_body<true >(2, alog, ds, sBC);
}

// ================= K4t: transpose wh planes + merge all 4 into g_ysum =========
__global__ void k4t_merge()
{
    __shared__ float s1[64 * 65];
    __shared__ float s3[64 * 65];
    const int tid = threadIdx.x;
    const int b = blockIdx.x / DIN;
    const int d = blockIdx.x % DIN;
    const float4* p0 = (const float4*)(g_y + ((size_t)(0 * BATCH + b) * DIN + d) * LSEQ);
    const float4* p1 = (const float4*)(g_y + ((size_t)(1 * BATCH + b) * DIN + d) * LSEQ);
    const float4* p2 = (const float4*)(g_y + ((size_t)(2 * BATCH + b) * DIN + d) * LSEQ);
    const float4* p3 = (const float4*)(g_y + ((size_t)(3 * BATCH + b) * DIN + d) * LSEQ);

    for (int t4 = tid; t4 < 1024; t4 += 256) {
        int i = t4 * 4;
        int w_ = i >> 6, h0 = i & 63;
        float4 v1 = p1[t4], v3 = p3[t4];
        s1[(h0 + 0) * 65 + w_] = v1.x; s1[(h0 + 1) * 65 + w_] = v1.y;
        s1[(h0 + 2) * 65 + w_] = v1.z; s1[(h0 + 3) * 65 + w_] = v1.w;
        s3[(h0 + 0) * 65 + w_] = v3.x; s3[(h0 + 1) * 65 + w_] = v3.y;
        s3[(h0 + 2) * 65 + w_] = v3.z; s3[(h0 + 3) * 65 + w_] = v3.w;
    }
    __syncthreads();

    float4* po = (float4*)(g_ysum + (size_t)(b * DIN + d) * LSEQ);
    for (int t4 = tid; t4 < 1024; t4 += 256) {
        int j = t4 * 4;
        int h = j >> 6, w0 = j & 63;
        float4 a = p0[t4], c = p2[t4];
        float4 r;
        r.x = a.x + c.x + s1[h * 65 + w0 + 0] + s3[h * 65 + w0 + 0];
        r.y = a.y + c.y + s1[h * 65 + w0 + 1] + s3[h * 65 + w0 + 1];
        r.z = a.z + c.z + s1[h * 65 + w0 + 2] + s3[h * 65 + w0 + 2];
        r.w = a.w + c.w + s1[h * 65 + w0 + 3] + s3[h * 65 + w0 + 3];
        po[t4] = r;
    }
}

// ================= K5: out-LN + gate + out_proj + residual (16 px/block) =======
__global__ void __launch_bounds__(256, 8) k5_final(const float* __restrict__ onw,
                                                   const float* __restrict__ onb,
                                                   const float* __restrict__ wout,
                                                   float* __restrict__ out)
{
    extern __shared__ float sm[];
    float* yc = sm;                  // 192*20 (padded)
    const int tid = threadIdx.x, lane = tid & 31, warp = tid >> 5;
    const int b = blockIdx.x >> 8;
    const int l0 = (blockIdx.x & 255) << 4;

    for (int i = tid; i < 192 * 16; i += 256) {
        int d = i >> 4, p = i & 15;
        yc[d * 20 + p] = g_ysum[(size_t)(b * DIN + d) * LSEQ + l0 + p];
    }
    __syncthreads();

    #pragma unroll
    for (int pp = 0; pp < 2; pp++) {
        const int p = warp * 2 + pp;
        float s = 0.f, s2 = 0.f, vv[6];
        #pragma unroll
        for (int j = 0; j < 6; j++) {
            float v = yc[(lane + 32 * j) * 20 + p];
            vv[j] = v; s += v; s2 += v * v;
        }
        #pragma unroll
        for (int o = 16; o > 0; o >>= 1) {
            s  += __shfl_xor_sync(0xffffffffu, s,  o);
            s2 += __shfl_xor_sync(0xffffffffu, s2, o);
        }
        float mu = s * (1.f / 192.f);
        float var = s2 * (1.f / 192.f) - mu * mu;
        float rstd = rsqrtf(var + 1e-5f);
        size_t zbase = ((size_t)(b * LSEQ + l0 + p)) * DIN;
        #pragma unroll
        for (int j = 0; j < 6; j++) {
            int dd = lane + 32 * j;
            float g = (vv[j] - mu) * rstd * onw[dd] + onb[dd];
            yc[dd * 20 + p] = g * g_zs[zbase + dd];
        }
    }
    __syncthreads();

    const int og = tid >> 3;   // 0..31: outs og*3..+2
    const int pg = tid & 7;    // pixel pair pg*2, pg*2+1
    u64 accp[3];
    accp[0] = accp[1] = accp[2] = 0ull;

    for (int dd4 = 0; dd4 < 192; dd4 += 4) {
        float4 w0 = __ldg((const float4*)(wout + (og * 3 + 0) * 192 + dd4));
        float4 w1 = __ldg((const float4*)(wout + (og * 3 + 1) * 192 + dd4));
        float4 w2 = __ldg((const float4*)(wout + (og * 3 + 2) * 192 + dd4));
        float w0a[4] = {w0.x, w0.y, w0.z, w0.w};
        float w1a[4] = {w1.x, w1.y, w1.z, w1.w};
        float w2a[4] = {w2.x, w2.y, w2.z, w2.w};
        #pragma unroll
        for (int j = 0; j < 4; j++) {
            u64 g = *(const u64*)&yc[(dd4 + j) * 20 + pg * 2];
            accp[0] = fma2(dup2(w0a[j]), g, accp[0]);
            accp[1] = fma2(dup2(w1a[j]), g, accp[1]);
            accp[2] = fma2(dup2(w2a[j]), g, accp[2]);
        }
    }
    __syncthreads();

    float* buf = sm;                 // 16 x 100 staging
    #pragma unroll
    for (int oi = 0; oi < 3; oi++) {
        float2 f = unp2(accp[oi]);
        buf[(pg * 2 + 0) * 100 + og * 3 + oi] = f.x;
        buf[(pg * 2 + 1) * 100 + og * 3 + oi] = f.y;
    }
    __syncthreads();

    const float4* df4 = (const float4*)(g_diff + ((size_t)b * LSEQ + l0) * CDIM);
    float4* out4 = (float4*)(out + ((size_t)b * LSEQ + l0) * CDIM);
    for (int t = tid; t < 16 * 24; t += 256) {
        int p = t / 24, o4 = t % 24;
        float4 v = *(const float4*)&buf[p * 100 + o4 * 4];
        float4 dv = df4[p * 24 + o4];
        v.x += dv.x; v.y += dv.y; v.z += dv.z; v.w += dv.w;
        out4[p * 24 + o4] = v;
    }
}

// ================= launch =================
extern "C" void kernel_launch(void* const* d_in, const int* in_sizes, int n_in,
                              void* d_out, int out_size)
{
    const float* x     = (const float*)d_in[0];
    const float* y     = (const float*)d_in[1];
    const float* ln_w  = (const float*)d_in[2];
    const float* ln_b  = (const float*)d_in[3];
    const float* ipw   = (const float*)d_in[4];
    const float* cw    = (const float*)d_in[5];
    const float* cb    = (const float*)d_in[6];
    const float* xpw   = (const float*)d_in[7];
    const float* dtw   = (const float*)d_in[8];
    const float* dtb   = (const float*)d_in[9];
    const float* alog  = (const float*)d_in[10];
    const float* ds    = (const float*)d_in[11];
    const float* onw   = (const float*)d_in[12];
    const float* onb   = (const float*)d_in[13];
    const float* wout  = (const float*)d_in[14];
    float* out = (float*)d_out;

    const int smem1 = (96 * 64 + 96 * 128) * 4;
    const int smem3 = (192 * 48 + 38 * 65 + 192 * 6 + 192) * 4;
    const int smem5 = (192 * 20) * 4;
    cudaFuncSetAttribute(k1_prologue, cudaFuncAttributeMaxDynamicSharedMemorySize, smem1);
    cudaFuncSetAttribute(k3_xproj,   cudaFuncAttributeMaxDynamicSharedMemorySize, smem3);
    cudaFuncSetAttribute(k5_final,   cudaFuncAttributeMaxDynamicSharedMemorySize, smem5);

    k1_prologue<<<dim3(128, 3), 256, smem1>>>(x, y, ln_w, ln_b, ipw);
    k2_conv<<<BATCH * DIN, 256>>>(cw, cb);
    k3_xproj<<<BATCH * 4 * (LSEQ / 64), 256, smem3>>>(xpw, dtw, dtb);
    k4a_scan<<<dim3(768, 2), 256>>>(alog);
    k4b_carry<<<NCH * NST / 256, 256>>>();
    k4c_scan<<<dim3(384, 2), 256>>>(alog, ds);
    k4t_merge<<<BATCH * DIN, 256>>>();
    k5_final<<<BATCH * (LSEQ / 16), 256, smem5>>>(onw, onb, wout, out);
}

// round 14
// speedup vs baseline: 1.0606x; 1.0143x over previous
#include <cuda_runtime.h>
#include <math.h>

#define BATCH 2
#define CDIM  96
#define DIN   192
#define NST   16
#define LSEQ  4096
#define NPIX  (BATCH*LSEQ)
#define NCH   (BATCH*4*DIN)
#define NCHUNK 32
#define CLEN  (LSEQ/NCHUNK)     // 128

typedef unsigned long long u64;

// ---------------- persistent device scratch ----------------
__device__ float  g_diff [NPIX*CDIM];
__device__ float  g_zs   [NPIX*DIN];
__device__ float  g_xm   [BATCH*DIN*LSEQ];
__device__ float  g_x0   [BATCH*DIN*LSEQ];
__device__ float  g_x1   [BATCH*DIN*LSEQ];
__device__ float  g_delta[BATCH*4*DIN*LSEQ];
__device__ float4 g_bb4  [BATCH*4*(LSEQ/4)*16];
__device__ float4 g_bc4  [BATCH*4*LSEQ*8];
__device__ float  g_y    [4*BATCH*DIN*LSEQ];
__device__ float  g_ysum [BATCH*DIN*LSEQ];
__device__ float  g_P    [NCH*NCHUNK*NST];
__device__ float  g_he   [NCH*NCHUNK*NST];
__device__ float  g_H    [NCH*NCHUNK*NST];

// ---- fast intrinsics ----
__device__ __forceinline__ float ex2(float x){ float r; asm("ex2.approx.f32 %0, %1;" : "=f"(r) : "f"(x)); return r; }
__device__ __forceinline__ float lg2(float x){ float r; asm("lg2.approx.f32 %0, %1;" : "=f"(r) : "f"(x)); return r; }
__device__ __forceinline__ float fexp(float x){ return ex2(x * 1.44269504f); }
__device__ __forceinline__ float silu_f(float v){ return v / (1.f + fexp(-v)); }

// ---- packed fp32x2 helpers (sm_103a) ----
__device__ __forceinline__ u64 dup2(float v) {
    u64 r; asm("mov.b64 %0, {%1, %1};" : "=l"(r) : "f"(v)); return r;
}
__device__ __forceinline__ u64 fma2(u64 a, u64 b, u64 c) {
    u64 d; asm("fma.rn.f32x2 %0, %1, %2, %3;" : "=l"(d) : "l"(a), "l"(b), "l"(c)); return d;
}
__device__ __forceinline__ u64 mul2(u64 a, u64 b) {
    u64 d; asm("mul.rn.f32x2 %0, %1, %2;" : "=l"(d) : "l"(a), "l"(b)); return d;
}
__device__ __forceinline__ u64 add2(u64 a, u64 b) {
    u64 d; asm("add.rn.f32x2 %0, %1, %2;" : "=l"(d) : "l"(a), "l"(b)); return d;
}
__device__ __forceinline__ float2 unp2(u64 v) {
    float2 r; asm("mov.b64 {%0, %1}, %2;" : "=f"(r.x), "=f"(r.y) : "l"(v)); return r;
}

// ================= K1: diff + LN + in_proj GEMM (f32x2) =================
__global__ void k1_prologue(const float* __restrict__ x, const float* __restrict__ y,
                            const float* __restrict__ lnw, const float* __restrict__ lnb,
                            const float* __restrict__ wproj)
{
    extern __shared__ float sm[];
    float* A_s = sm;            // 96*64
    float* W_s = sm + 96*64;    // 96*128
    const int tid = threadIdx.x, lane = tid & 31, warp = tid >> 5;
    const int pix0 = blockIdx.x * 64;
    const int oc = blockIdx.y;

    for (int pp = 0; pp < 8; pp++) {
        const int p = warp * 8 + pp;
        const int base = (pix0 + p) * CDIM;
        float vv[3]; float s = 0.f, s2 = 0.f;
        #pragma unroll
        for (int j = 0; j < 3; j++) {
            int ch = lane + 32 * j;
            float d = fabsf(x[base + ch] - y[base + ch]);
            if (oc == 0) g_diff[base + ch] = d;
            vv[j] = d; s += d; s2 += d * d;
        }
        #pragma unroll
        for (int o = 16; o > 0; o >>= 1) {
            s  += __shfl_xor_sync(0xffffffffu, s,  o);
            s2 += __shfl_xor_sync(0xffffffffu, s2, o);
        }
        float mu = s * (1.f / 96.f);
        float var = s2 * (1.f / 96.f) - mu * mu;
        float rstd = rsqrtf(var + 1e-5f);
        #pragma unroll
        for (int j = 0; j < 3; j++) {
            int ch = lane + 32 * j;
            A_s[ch * 64 + p] = (vv[j] - mu) * rstd * lnw[ch] + lnb[ch];
        }
    }
    for (int i = tid; i < 96 * 128; i += 256) {
        int kk = i % 96, j = i / 96;
        W_s[kk * 128 + j] = wproj[(oc * 128 + j) * 96 + kk];
    }
    __syncthreads();

    const int pg = tid & 7;
    const int og = tid >> 3;
    const float4* W4 = (const float4*)W_s;

    u64 accp[4][4];
    #pragma unroll
    for (int a = 0; a < 4; a++)
        #pragma unroll
        for (int b = 0; b < 4; b++) accp[a][b] = 0ull;

    #pragma unroll 4
    for (int kk = 0; kk < 96; kk++) {
        const ulonglong2* ap = (const ulonglong2*)(A_s + kk * 64 + pg * 8);
        ulonglong2 a01 = ap[0], a23 = ap[1];
        float4 w = W4[kk * 32 + og];
        u64 wd[4] = {dup2(w.x), dup2(w.y), dup2(w.z), dup2(w.w)};
        #pragma unroll
        for (int jj = 0; jj < 4; jj++) {
            accp[jj][0] = fma2(wd[jj], a01.x, accp[jj][0]);
            accp[jj][1] = fma2(wd[jj], a01.y, accp[jj][1]);
            accp[jj][2] = fma2(wd[jj], a23.x, accp[jj][2]);
            accp[jj][3] = fma2(wd[jj], a23.y, accp[jj][3]);
        }
    }

    float acc[4][8];
    #pragma unroll
    for (int jj = 0; jj < 4; jj++) {
        #pragma unroll
        for (int pr = 0; pr < 4; pr++) {
            float2 f = unp2(accp[jj][pr]);
            acc[jj][pr * 2] = f.x; acc[jj][pr * 2 + 1] = f.y;
        }
    }

    const int jg0 = oc * 128 + og * 4;
    const int pixb = pix0 + pg * 8;
    const int bb = pixb >> 12, lb = pixb & 4095;
    if (jg0 + 3 < DIN) {
        #pragma unroll
        for (int jj = 0; jj < 4; jj++) {
            float* row = g_xm + (size_t)(bb * DIN + jg0 + jj) * LSEQ + lb;
            *(float4*)row       = make_float4(acc[jj][0], acc[jj][1], acc[jj][2], acc[jj][3]);
            *(float4*)(row + 4) = make_float4(acc[jj][4], acc[jj][5], acc[jj][6], acc[jj][7]);
        }
    } else {
        const int zc = jg0 - DIN;
        #pragma unroll
        for (int pi = 0; pi < 8; pi++) {
            float* zp = g_zs + (size_t)(pixb + pi) * DIN + zc;
            *(float4*)zp = make_float4(silu_f(acc[0][pi]), silu_f(acc[1][pi]),
                                       silu_f(acc[2][pi]), silu_f(acc[3][pi]));
        }
    }
}

// ================= K2: depthwise conv + silu =================
__global__ void k2_conv(const float* __restrict__ cw, const float* __restrict__ cb)
{
    __shared__ float tin [64 * 65];
    __shared__ float tout[64 * 65];
    const int tid = threadIdx.x;
    const int bd = blockIdx.x;
    const int d = bd % DIN;
    const float* src = g_xm + (size_t)bd * LSEQ;

    for (int t = tid; t < 1024; t += 256) {
        float4 v = ((const float4*)src)[t];
        int i = t * 4;
        int h = i >> 6, w = i & 63;
        float* p = &tin[h * 65 + w];
        p[0] = v.x; p[1] = v.y; p[2] = v.z; p[3] = v.w;
    }
    float wreg[9];
    #pragma unroll
    for (int i = 0; i < 9; i++) wreg[i] = cw[d * 9 + i];
    const float bias = cb[d];
    __syncthreads();

    float* dst0 = g_x0 + (size_t)bd * LSEQ;
    for (int t = tid; t < 4096; t += 256) {
        int h = t >> 6, w = t & 63;
        float acc = bias;
        #pragma unroll
        for (int dy = 0; dy < 3; dy++) {
            int hh = h + dy - 1;
            if (hh < 0 || hh > 63) continue;
            #pragma unroll
            for (int dx = 0; dx < 3; dx++) {
                int ww = w + dx - 1;
                if (ww < 0 || ww > 63) continue;
                acc = fmaf(tin[hh * 65 + ww], wreg[dy * 3 + dx], acc);
            }
        }
        float v = silu_f(acc);
        dst0[t] = v;
        tout[h * 65 + w] = v;
    }
    __syncthreads();

    float* dst1 = g_x1 + (size_t)bd * LSEQ;
    for (int t = tid; t < 4096; t += 256) {
        int w = t >> 6, h = t & 63;
        dst1[t] = tout[h * 65 + w];
    }
}

// ================= K3: x_proj + dt_proj + softplus =================
__global__ void __launch_bounds__(256, 4) k3_xproj(const float* __restrict__ xpw,
                                                   const float* __restrict__ dtw,
                                                   const float* __restrict__ dtb)
{
    extern __shared__ float sm[];
    float* wp_t = sm;                         // 192*48
    float* xd_s = wp_t + 192 * 48;            // 38*65
    float* dw_s = xd_s + 38 * 65;             // 192*6
    float* db_s = dw_s + 192 * 6;             // 192
    const int tid = threadIdx.x;
    const int bk = blockIdx.x >> 6;
    const int b = bk >> 2, k = bk & 3;
    const int l0 = (blockIdx.x & 63) << 6;
    const float* seq = (k & 1) ? g_x1 : g_x0;

    for (int i = tid; i < 192 * 48; i += 256) wp_t[i] = 0.f;
    __syncthreads();

    for (int i = tid; i < 38 * 192; i += 256) {
        int kk = i % 192, row = i / 192;
        wp_t[kk * 48 + row] = xpw[k * 38 * 192 + i];
    }
    for (int i = tid; i < 192 * 6;  i += 256) dw_s[i] = dtw[k * 192 * 6 + i];
    for (int i = tid; i < 192;      i += 256) db_s[i] = dtb[k * DIN + i];
    __syncthreads();

    const int col = tid & 63, grp = tid >> 6;
    const float* up = seq + (size_t)b * DIN * LSEQ + l0 + col;
    u64 accp[6];
    #pragma unroll
    for (int j = 0; j < 6; j++) accp[j] = 0ull;
    #pragma unroll 2
    for (int kk = 0; kk < 192; kk++) {
        float uv = __ldg(up + (size_t)kk * LSEQ);
        u64 ud = dup2(uv);
        const ulonglong2* wp2 = (const ulonglong2*)(wp_t + kk * 48 + grp * 12);
        ulonglong2 wA = wp2[0], wB = wp2[1], wC = wp2[2];
        accp[0] = fma2(wA.x, ud, accp[0]);
        accp[1] = fma2(wA.y, ud, accp[1]);
        accp[2] = fma2(wB.x, ud, accp[2]);
        accp[3] = fma2(wB.y, ud, accp[3]);
        accp[4] = fma2(wC.x, ud, accp[4]);
        accp[5] = fma2(wC.y, ud, accp[5]);
    }
    #pragma unroll
    for (int j = 0; j < 6; j++) {
        float2 f = unp2(accp[j]);
        int row0 = grp * 12 + j * 2;
        if (row0 < 38)     xd_s[row0 * 65 + col] = f.x;
        if (row0 + 1 < 38) xd_s[(row0 + 1) * 65 + col] = f.y;
    }
    __syncthreads();

    const size_t lb4 = (size_t)bk * 1024 + (l0 >> 2);
    for (int i = tid; i < 16 * 64; i += 256) {
        int n = i & 15, cc = i >> 4;
        ((float*)g_bb4)[((lb4 + (cc >> 2)) * 16 + n) * 4 + (cc & 3)] = xd_s[(6 + n) * 65 + cc];
    }
    const size_t bcbase = (size_t)bk * LSEQ + l0;
    for (int i = tid; i < 8 * 64; i += 256) {
        int n8 = i & 7, cc = i >> 3;
        float4 v;
        v.x = xd_s[(6  + n8) * 65 + cc];
        v.y = xd_s[(22 + n8) * 65 + cc];
        v.z = xd_s[(14 + n8) * 65 + cc];
        v.w = xd_s[(30 + n8) * 65 + cc];
        g_bc4[(bcbase + cc) * 8 + n8] = v;
    }
    float xdv[6];
    #pragma unroll
    for (int r = 0; r < 6; r++) xdv[r] = xd_s[r * 65 + col];
    const int dg = tid >> 6;
    const size_t dbase = (size_t)bk * DIN * LSEQ;
    for (int j = 0; j < 48; j++) {
        int d = dg + 4 * j;
        float val = db_s[d];
        #pragma unroll
        for (int r = 0; r < 6; r++)
            val = fmaf(dw_s[d * 6 + r], xdv[r], val);
        float t = fexp(-fabsf(val));
        val = fmaxf(val, 0.f) + lg2(1.f + t) * 0.69314718f;
        g_delta[dbase + (size_t)d * LSEQ + l0 + col] = val;
    }
}

// ================= K4a: local chunk scan (NCHUNK=32) =================
template<bool REV>
__device__ __forceinline__ void k4a_body(const int K0, const float* __restrict__ alog,
                                         float4* sB)
{
    const int tid = threadIdx.x;
    const int lane = tid & 31, wi = tid >> 5;
    int bx = blockIdx.x;
    const int pb = bx % 12; bx /= 12;
    const int chunk = bx & 31; bx >>= 5;
    const int kk = bx & 1;
    const int b  = bx >> 1;
    const int p = pb * 8 + wi;
    const int half = lane >> 4, n = lane & 15;
    const int d = p * 2 + half;
    const int k = K0 + kk;
    const int bk = b * 4 + k;
    const int ch = bk * DIN + d;
    const float An2 = -fexp(alog[(k * DIN + d) * NST + n]) * 1.44269504f;
    const u64 An2d = dup2(An2);

    // stage B tile: CLEN/4 = 32 lblks x 16 n = 512 float4 = 8KB
    {
        const int tb = REV ? (1024 - (chunk + 1) * 32) : chunk * 32;
        const float4* src = g_bb4 + ((size_t)bk * 1024 + tb) * 16;
        #pragma unroll
        for (int i = 0; i < 2; i++) sB[tid + i * 256] = src[tid + i * 256];
    }
    __syncthreads();

    const float* dptr = g_delta + ((size_t)bk * DIN + d) * LSEQ;
    const float* uptr = (kk ? g_x1 : g_x0) + ((size_t)b * DIN + d) * LSEQ;

    float h = 0.f;
    u64 sdel2 = 0ull;
    if (!REV) {
        const int i0 = chunk * CLEN;
        const ulonglong2* dp2 = (const ulonglong2*)(dptr + i0);
        const ulonglong2* up2 = (const ulonglong2*)(uptr + i0);
        #pragma unroll 4
        for (int s = 0; s < CLEN / 4; s++) {
            ulonglong2 dp = dp2[s], up = up2[s];
            float4 b4 = sB[s * 16 + n];
            u64 e01  = mul2(dp.x, An2d), e23  = mul2(dp.y, An2d);
            u64 du01 = mul2(dp.x, up.x), du23 = mul2(dp.y, up.y);
            sdel2 = add2(sdel2, dp.x); sdel2 = add2(sdel2, dp.y);
            float2 e0 = unp2(e01), e2 = unp2(e23);
            float2 dA = unp2(du01), dB = unp2(du23);
            h = fmaf(ex2(e0.x), h, dA.x * b4.x);
            h = fmaf(ex2(e0.y), h, dA.y * b4.y);
            h = fmaf(ex2(e2.x), h, dB.x * b4.z);
            h = fmaf(ex2(e2.y), h, dB.y * b4.w);
        }
    } else {
        const int ltop = LSEQ - chunk * CLEN;
        const ulonglong2* dp2 = (const ulonglong2*)(dptr + ltop) - 1;
        const ulonglong2* up2 = (const ulonglong2*)(uptr + ltop) - 1;
        #pragma unroll 4
        for (int s = 0; s < CLEN / 4; s++) {
            ulonglong2 dp = dp2[-s], up = up2[-s];
            float4 b4 = sB[(CLEN / 4 - 1 - s) * 16 + n];
            u64 e01  = mul2(dp.x, An2d), e23  = mul2(dp.y, An2d);
            u64 du01 = mul2(dp.x, up.x), du23 = mul2(dp.y, up.y);
            sdel2 = add2(sdel2, dp.x); sdel2 = add2(sdel2, dp.y);
            float2 e0 = unp2(e01), e2 = unp2(e23);
            float2 dA = unp2(du01), dB = unp2(du23);
            h = fmaf(ex2(e2.y), h, dB.y * b4.w);
            h = fmaf(ex2(e2.x), h, dB.x * b4.z);
            h = fmaf(ex2(e0.y), h, dA.y * b4.y);
            h = fmaf(ex2(e0.x), h, dA.x * b4.x);
        }
    }
    float2 sd = unp2(sdel2);
    g_P [(ch * NCHUNK + chunk) * NST + n] = ex2(An2 * (sd.x + sd.y));
    g_he[(ch * NCHUNK + chunk) * NST + n] = h;
}

__global__ void __launch_bounds__(256, 6) k4a_scan(const float* __restrict__ alog)
{
    __shared__ float4 sB[512];
    if (blockIdx.y == 0) k4a_body<false>(0, alog, sB);
    else                 k4a_body<true >(2, alog, sB);
}

// ================= K4b: carry across chunks =================
__global__ void k4b_carry()
{
    int idx = blockIdx.x * 256 + threadIdx.x;
    int ch = idx >> 4, n = idx & 15;
    float H = 0.f;
    #pragma unroll
    for (int c = 0; c < NCHUNK; c++) {
        int o = (ch * NCHUNK + c) * NST + n;
        g_H[o] = H;
        H = fmaf(g_P[o], H, g_he[o]);
    }
}

// ================= K4c: seeded scan, emit y (NCHUNK=32, 3-shuffle) =========
template<bool REV>
__device__ __forceinline__ void k4c_body(const int K0, const float* __restrict__ alog,
                                         const float* __restrict__ ds, float4* sBC)
{
    const int tid = threadIdx.x;
    const int lane = tid & 31, wi = tid >> 5;
    int bx = blockIdx.x;
    const int qb = bx % 6; bx /= 6;
    const int chunk = bx & 31; bx >>= 5;
    const int kk = bx & 1;
    const int b  = bx >> 1;
    const int q = qb * 8 + wi;
    const int c2 = lane >> 3;
    const int n0 = lane & 7;
    const int d = q * 4 + c2;
    const int k = K0 + kk;
    const int bk = b * 4 + k;
    const int ch = bk * DIN + d;

    // stage BC tile: CLEN x 8 = 1024 float4 = 16KB
    {
        const int lt0 = REV ? (LSEQ - (chunk + 1) * CLEN) : chunk * CLEN;
        const float4* src = g_bc4 + ((size_t)bk * LSEQ + lt0) * 8;
        #pragma unroll
        for (int i = 0; i < 4; i++) sBC[tid + i * 256] = src[tid + i * 256];
    }
    __syncthreads();

    const float An0 = -fexp(alog[(k * DIN + d) * NST + n0]) * 1.44269504f;
    const float An1 = -fexp(alog[(k * DIN + d) * NST + n0 + 8]) * 1.44269504f;
    const u64 An0d = dup2(An0), An1d = dup2(An1);
    const float Dd = ds[k * DIN + d];
    const u64 Ddd = dup2(Dd);

    const float* dptr = g_delta + ((size_t)bk * DIN + d) * LSEQ;
    const float* uptr = (kk ? g_x1 : g_x0) + ((size_t)b * DIN + d) * LSEQ;
    float* yp = g_y + ((size_t)(k * BATCH + b) * DIN + d) * LSEQ;

    float h0 = g_H[(ch * NCHUNK + chunk) * NST + n0];
    float h1 = g_H[(ch * NCHUNK + chunk) * NST + n0 + 8];

    if (!REV) {
        const int i0 = chunk * CLEN;
        const ulonglong2* dp2 = (const ulonglong2*)(dptr + i0);
        const ulonglong2* up2 = (const ulonglong2*)(uptr + i0);
        float4* yp4 = (float4*)(yp + i0);
        #pragma unroll 4
        for (int s = 0; s < CLEN / 4; s++) {
            ulonglong2 dp = dp2[s], up = up2[s];
            u64 eA01 = mul2(dp.x, An0d), eA23 = mul2(dp.y, An0d);
            u64 eB01 = mul2(dp.x, An1d), eB23 = mul2(dp.y, An1d);
            u64 du01 = mul2(dp.x, up.x), du23 = mul2(dp.y, up.y);
            u64 gu01 = mul2(up.x, Ddd),  gu23 = mul2(up.y, Ddd);
            float2 eA0 = unp2(eA01), eA2 = unp2(eA23);
            float2 eB0 = unp2(eB01), eB2 = unp2(eB23);
            float2 duA = unp2(du01), duB = unp2(du23);
            float2 guA = unp2(gu01), guB = unp2(gu23);
            float eAj[4] = {eA0.x, eA0.y, eA2.x, eA2.y};
            float eBj[4] = {eB0.x, eB0.y, eB2.x, eB2.y};
            float duj[4] = {duA.x, duA.y, duB.x, duB.y};
            float guj[4] = {guA.x, guA.y, guB.x, guB.y};
            float tr[4];
            #pragma unroll
            for (int j = 0; j < 4; j++) {
                float4 bc = sBC[(s * 4 + j) * 8 + n0];
                h0 = fmaf(ex2(eAj[j]), h0, duj[j] * bc.x);
                h1 = fmaf(ex2(eBj[j]), h1, duj[j] * bc.z);
                float t = fmaf(h1, bc.w, h0 * bc.y);
                t += __shfl_xor_sync(0xffffffffu, t, 4);
                t += __shfl_xor_sync(0xffffffffu, t, 2);
                t += __shfl_xor_sync(0xffffffffu, t, 1);
                tr[j] = guj[j] + t;
            }
            if (n0 == 0) yp4[s] = make_float4(tr[0], tr[1], tr[2], tr[3]);
        }
    } else {
        const int ltop = LSEQ - chunk * CLEN;
        const ulonglong2* dp2 = (const ulonglong2*)(dptr + ltop) - 1;
        const ulonglong2* up2 = (const ulonglong2*)(uptr + ltop) - 1;
        float4* yp4 = (float4*)(yp + ltop) - 1;
        #pragma unroll 4
        for (int s = 0; s < CLEN / 4; s++) {
            ulonglong2 dp = dp2[-s], up = up2[-s];
            u64 eA01 = mul2(dp.x, An0d), eA23 = mul2(dp.y, An0d);
            u64 eB01 = mul2(dp.x, An1d), eB23 = mul2(dp.y, An1d);
            u64 du01 = mul2(dp.x, up.x), du23 = mul2(dp.y, up.y);
            u64 gu01 = mul2(up.x, Ddd),  gu23 = mul2(up.y, Ddd);
            float2 eA0 = unp2(eA01), eA2 = unp2(eA23);
            float2 eB0 = unp2(eB01), eB2 = unp2(eB23);
            float2 duA = unp2(du01), duB = unp2(du23);
            float2 guA = unp2(gu01), guB = unp2(gu23);
            float eAj[4] = {eA0.x, eA0.y, eA2.x, eA2.y};
            float eBj[4] = {eB0.x, eB0.y, eB2.x, eB2.y};
            float duj[4] = {duA.x, duA.y, duB.x, duB.y};
            float guj[4] = {guA.x, guA.y, guB.x, guB.y};
            float tr[4];
            #pragma unroll
            for (int j = 3; j >= 0; j--) {
                float4 bc = sBC[(CLEN - 1 - (s * 4 + (3 - j))) * 8 + n0];
                h0 = fmaf(ex2(eAj[j]), h0, duj[j] * bc.x);
                h1 = fmaf(ex2(eBj[j]), h1, duj[j] * bc.z);
                float t = fmaf(h1, bc.w, h0 * bc.y);
                t += __shfl_xor_sync(0xffffffffu, t, 4);
                t += __shfl_xor_sync(0xffffffffu, t, 2);
                t += __shfl_xor_sync(0xffffffffu, t, 1);
                tr[j] = guj[j] + t;
            }
            if (n0 == 0) yp4[-s] = make_float4(tr[0], tr[1], tr[2], tr[3]);
        }
    }
}

__global__ void __launch_bounds__(256, 6) k4c_scan(const float* __restrict__ alog,
                                                   const float* __restrict__ ds)
{
    __shared__ float4 sBC[1024];
    if (blockIdx.y == 0) k4c_body<false>(0, alog, ds, sBC);
    else                 k4c_body<true >(2, alog, ds, sBC);
}

// ================= K4t: transpose wh planes + merge all 4 into g_ysum =========
__global__ void k4t_merge()
{
    __shared__ float s1[64 * 65];
    __shared__ float s3[64 * 65];
    const int tid = threadIdx.x;
    const int b = blockIdx.x / DIN;
    const int d = blockIdx.x % DIN;
    const float4* p0 = (const float4*)(g_y + ((size_t)(0 * BATCH + b) * DIN + d) * LSEQ);
    const float4* p1 = (const float4*)(g_y + ((size_t)(1 * BATCH + b) * DIN + d) * LSEQ);
    const float4* p2 = (const float4*)(g_y + ((size_t)(2 * BATCH + b) * DIN + d) * LSEQ);
    const float4* p3 = (const float4*)(g_y + ((size_t)(3 * BATCH + b) * DIN + d) * LSEQ);

    for (int t4 = tid; t4 < 1024; t4 += 256) {
        int i = t4 * 4;
        int w_ = i >> 6, h0 = i & 63;
        float4 v1 = p1[t4], v3 = p3[t4];
        s1[(h0 + 0) * 65 + w_] = v1.x; s1[(h0 + 1) * 65 + w_] = v1.y;
        s1[(h0 + 2) * 65 + w_] = v1.z; s1[(h0 + 3) * 65 + w_] = v1.w;
        s3[(h0 + 0) * 65 + w_] = v3.x; s3[(h0 + 1) * 65 + w_] = v3.y;
        s3[(h0 + 2) * 65 + w_] = v3.z; s3[(h0 + 3) * 65 + w_] = v3.w;
    }
    __syncthreads();

    float4* po = (float4*)(g_ysum + (size_t)(b * DIN + d) * LSEQ);
    for (int t4 = tid; t4 < 1024; t4 += 256) {
        int j = t4 * 4;
        int h = j >> 6, w0 = j & 63;
        float4 a = p0[t4], c = p2[t4];
        float4 r;
        r.x = a.x + c.x + s1[h * 65 + w0 + 0] + s3[h * 65 + w0 + 0];
        r.y = a.y + c.y + s1[h * 65 + w0 + 1] + s3[h * 65 + w0 + 1];
        r.z = a.z + c.z + s1[h * 65 + w0 + 2] + s3[h * 65 + w0 + 2];
        r.w = a.w + c.w + s1[h * 65 + w0 + 3] + s3[h * 65 + w0 + 3];
        po[t4] = r;
    }
}

// ================= K5: out-LN + gate + out_proj + residual (16 px/block) =======
__global__ void __launch_bounds__(256, 8) k5_final(const float* __restrict__ onw,
                                                   const float* __restrict__ onb,
                                                   const float* __restrict__ wout,
                                                   float* __restrict__ out)
{
    extern __shared__ float sm[];
    float* yc = sm;                  // 192*20 (padded)
    const int tid = threadIdx.x, lane = tid & 31, warp = tid >> 5;
    const int b = blockIdx.x >> 8;
    const int l0 = (blockIdx.x & 255) << 4;

    for (int i = tid; i < 192 * 16; i += 256) {
        int d = i >> 4, p = i & 15;
        yc[d * 20 + p] = g_ysum[(size_t)(b * DIN + d) * LSEQ + l0 + p];
    }
    __syncthreads();

    #pragma unroll
    for (int pp = 0; pp < 2; pp++) {
        const int p = warp * 2 + pp;
        float s = 0.f, s2 = 0.f, vv[6];
        #pragma unroll
        for (int j = 0; j < 6; j++) {
            float v = yc[(lane + 32 * j) * 20 + p];
            vv[j] = v; s += v; s2 += v * v;
        }
        #pragma unroll
        for (int o = 16; o > 0; o >>= 1) {
            s  += __shfl_xor_sync(0xffffffffu, s,  o);
            s2 += __shfl_xor_sync(0xffffffffu, s2, o);
        }
        float mu = s * (1.f / 192.f);
        float var = s2 * (1.f / 192.f) - mu * mu;
        float rstd = rsqrtf(var + 1e-5f);
        size_t zbase = ((size_t)(b * LSEQ + l0 + p)) * DIN;
        #pragma unroll
        for (int j = 0; j < 6; j++) {
            int dd = lane + 32 * j;
            float g = (vv[j] - mu) * rstd * onw[dd] + onb[dd];
            yc[dd * 20 + p] = g * g_zs[zbase + dd];
        }
    }
    __syncthreads();

    const int og = tid >> 3;
    const int pg = tid & 7;
    u64 accp[3];
    accp[0] = accp[1] = accp[2] = 0ull;

    for (int dd4 = 0; dd4 < 192; dd4 += 4) {
        float4 w0 = __ldg((const float4*)(wout + (og * 3 + 0) * 192 + dd4));
        float4 w1 = __ldg((const float4*)(wout + (og * 3 + 1) * 192 + dd4));
        float4 w2 = __ldg((const float4*)(wout + (og * 3 + 2) * 192 + dd4));
        float w0a[4] = {w0.x, w0.y, w0.z, w0.w};
        float w1a[4] = {w1.x, w1.y, w1.z, w1.w};
        float w2a[4] = {w2.x, w2.y, w2.z, w2.w};
        #pragma unroll
        for (int j = 0; j < 4; j++) {
            u64 g = *(const u64*)&yc[(dd4 + j) * 20 + pg * 2];
            accp[0] = fma2(dup2(w0a[j]), g, accp[0]);
            accp[1] = fma2(dup2(w1a[j]), g, accp[1]);
            accp[2] = fma2(dup2(w2a[j]), g, accp[2]);
        }
    }
    __syncthreads();

    float* buf = sm;                 // 16 x 100 staging
    #pragma unroll
    for (int oi = 0; oi < 3; oi++) {
        float2 f = unp2(accp[oi]);
        buf[(pg * 2 + 0) * 100 + og * 3 + oi] = f.x;
        buf[(pg * 2 + 1) * 100 + og * 3 + oi] = f.y;
    }
    __syncthreads();

    const float4* df4 = (const float4*)(g_diff + ((size_t)b * LSEQ + l0) * CDIM);
    float4* out4 = (float4*)(out + ((size_t)b * LSEQ + l0) * CDIM);
    for (int t = tid; t < 16 * 24; t += 256) {
        int p = t / 24, o4 = t % 24;
        float4 v = *(const float4*)&buf[p * 100 + o4 * 4];
        float4 dv = df4[p * 24 + o4];
        v.x += dv.x; v.y += dv.y; v.z += dv.z; v.w += dv.w;
        out4[p * 24 + o4] = v;
    }
}

// ================= launch =================
extern "C" void kernel_launch(void* const* d_in, const int* in_sizes, int n_in,
                              void* d_out, int out_size)
{
    const float* x     = (const float*)d_in[0];
    const float* y     = (const float*)d_in[1];
    const float* ln_w  = (const float*)d_in[2];
    const float* ln_b  = (const float*)d_in[3];
    const float* ipw   = (const float*)d_in[4];
    const float* cw    = (const float*)d_in[5];
    const float* cb    = (const float*)d_in[6];
    const float* xpw   = (const float*)d_in[7];
    const float* dtw   = (const float*)d_in[8];
    const float* dtb   = (const float*)d_in[9];
    const float* alog  = (const float*)d_in[10];
    const float* ds    = (const float*)d_in[11];
    const float* onw   = (const float*)d_in[12];
    const float* onb   = (const float*)d_in[13];
    const float* wout  = (const float*)d_in[14];
    float* out = (float*)d_out;

    const int smem1 = (96 * 64 + 96 * 128) * 4;
    const int smem3 = (192 * 48 + 38 * 65 + 192 * 6 + 192) * 4;
    const int smem5 = (192 * 20) * 4;
    cudaFuncSetAttribute(k1_prologue, cudaFuncAttributeMaxDynamicSharedMemorySize, smem1);
    cudaFuncSetAttribute(k3_xproj,   cudaFuncAttributeMaxDynamicSharedMemorySize, smem3);
    cudaFuncSetAttribute(k5_final,   cudaFuncAttributeMaxDynamicSharedMemorySize, smem5);

    k1_prologue<<<dim3(128, 3), 256, smem1>>>(x, y, ln_w, ln_b, ipw);
    k2_conv<<<BATCH * DIN, 256>>>(cw, cb);
    k3_xproj<<<BATCH * 4 * (LSEQ / 64), 256, smem3>>>(xpw, dtw, dtb);
    // k4a: 12 pair-blocks x 32 chunks x 2 kk x 2 b = 1536 per direction
    k4a_scan<<<dim3(1536, 2), 256>>>(alog);
    k4b_carry<<<NCH * NST / 256, 256>>>();
    // k4c: 6 quad-blocks x 32 chunks x 2 kk x 2 b = 768 per direction
    k4c_scan<<<dim3(768, 2), 256>>>(alog, ds);
    k4t_merge<<<BATCH * DIN, 256>>>();
    k5_final<<<BATCH * (LSEQ / 16), 256, smem5>>>(onw, onb, wout, out);
}

// round 15
// speedup vs baseline: 1.0765x; 1.0149x over previous
#include <cuda_runtime.h>
#include <math.h>

#define BATCH 2
#define CDIM  96
#define DIN   192
#define NST   16
#define LSEQ  4096
#define NPIX  (BATCH*LSEQ)
#define NCH   (BATCH*4*DIN)
#define NCHUNK 32
#define CLEN  (LSEQ/NCHUNK)     // 128

typedef unsigned long long u64;

// ---------------- persistent device scratch ----------------
__device__ float  g_diff [NPIX*CDIM];
__device__ float  g_zs   [NPIX*DIN];
__device__ float  g_xm   [BATCH*DIN*LSEQ];
__device__ float  g_x0   [BATCH*DIN*LSEQ];
__device__ float  g_x1   [BATCH*DIN*LSEQ];
__device__ float  g_delta[BATCH*4*DIN*LSEQ];
__device__ float4 g_bb4  [BATCH*4*(LSEQ/4)*16];
__device__ float4 g_bc4  [BATCH*4*LSEQ*8];
__device__ float  g_y    [4*BATCH*DIN*LSEQ];
__device__ float  g_ysum [BATCH*DIN*LSEQ];
__device__ float  g_P    [NCH*NCHUNK*NST];
__device__ float  g_he   [NCH*NCHUNK*NST];
__device__ float  g_H    [NCH*NCHUNK*NST];

// ---- fast intrinsics ----
__device__ __forceinline__ float ex2(float x){ float r; asm("ex2.approx.f32 %0, %1;" : "=f"(r) : "f"(x)); return r; }
__device__ __forceinline__ float lg2(float x){ float r; asm("lg2.approx.f32 %0, %1;" : "=f"(r) : "f"(x)); return r; }
__device__ __forceinline__ float fexp(float x){ return ex2(x * 1.44269504f); }
__device__ __forceinline__ float silu_f(float v){ return v / (1.f + fexp(-v)); }

// ---- packed fp32x2 helpers (sm_103a) ----
__device__ __forceinline__ u64 dup2(float v) {
    u64 r; asm("mov.b64 %0, {%1, %1};" : "=l"(r) : "f"(v)); return r;
}
__device__ __forceinline__ u64 fma2(u64 a, u64 b, u64 c) {
    u64 d; asm("fma.rn.f32x2 %0, %1, %2, %3;" : "=l"(d) : "l"(a), "l"(b), "l"(c)); return d;
}
__device__ __forceinline__ u64 mul2(u64 a, u64 b) {
    u64 d; asm("mul.rn.f32x2 %0, %1, %2;" : "=l"(d) : "l"(a), "l"(b)); return d;
}
__device__ __forceinline__ u64 add2(u64 a, u64 b) {
    u64 d; asm("add.rn.f32x2 %0, %1, %2;" : "=l"(d) : "l"(a), "l"(b)); return d;
}
__device__ __forceinline__ float2 unp2(u64 v) {
    float2 r; asm("mov.b64 {%0, %1}, %2;" : "=f"(r.x), "=f"(r.y) : "l"(v)); return r;
}

// ================= K1: diff + LN + in_proj GEMM (f32x2) =================
__global__ void k1_prologue(const float* __restrict__ x, const float* __restrict__ y,
                            const float* __restrict__ lnw, const float* __restrict__ lnb,
                            const float* __restrict__ wproj)
{
    extern __shared__ float sm[];
    float* A_s = sm;            // 96*64
    float* W_s = sm + 96*64;    // 96*128
    const int tid = threadIdx.x, lane = tid & 31, warp = tid >> 5;
    const int pix0 = blockIdx.x * 64;
    const int oc = blockIdx.y;

    for (int pp = 0; pp < 8; pp++) {
        const int p = warp * 8 + pp;
        const int base = (pix0 + p) * CDIM;
        float vv[3]; float s = 0.f, s2 = 0.f;
        #pragma unroll
        for (int j = 0; j < 3; j++) {
            int ch = lane + 32 * j;
            float d = fabsf(x[base + ch] - y[base + ch]);
            if (oc == 0) g_diff[base + ch] = d;
            vv[j] = d; s += d; s2 += d * d;
        }
        #pragma unroll
        for (int o = 16; o > 0; o >>= 1) {
            s  += __shfl_xor_sync(0xffffffffu, s,  o);
            s2 += __shfl_xor_sync(0xffffffffu, s2, o);
        }
        float mu = s * (1.f / 96.f);
        float var = s2 * (1.f / 96.f) - mu * mu;
        float rstd = rsqrtf(var + 1e-5f);
        #pragma unroll
        for (int j = 0; j < 3; j++) {
            int ch = lane + 32 * j;
            A_s[ch * 64 + p] = (vv[j] - mu) * rstd * lnw[ch] + lnb[ch];
        }
    }
    for (int i = tid; i < 96 * 128; i += 256) {
        int kk = i % 96, j = i / 96;
        W_s[kk * 128 + j] = wproj[(oc * 128 + j) * 96 + kk];
    }
    __syncthreads();

    const int pg = tid & 7;
    const int og = tid >> 3;
    const float4* W4 = (const float4*)W_s;

    u64 accp[4][4];
    #pragma unroll
    for (int a = 0; a < 4; a++)
        #pragma unroll
        for (int b = 0; b < 4; b++) accp[a][b] = 0ull;

    #pragma unroll 4
    for (int kk = 0; kk < 96; kk++) {
        const ulonglong2* ap = (const ulonglong2*)(A_s + kk * 64 + pg * 8);
        ulonglong2 a01 = ap[0], a23 = ap[1];
        float4 w = W4[kk * 32 + og];
        u64 wd[4] = {dup2(w.x), dup2(w.y), dup2(w.z), dup2(w.w)};
        #pragma unroll
        for (int jj = 0; jj < 4; jj++) {
            accp[jj][0] = fma2(wd[jj], a01.x, accp[jj][0]);
            accp[jj][1] = fma2(wd[jj], a01.y, accp[jj][1]);
            accp[jj][2] = fma2(wd[jj], a23.x, accp[jj][2]);
            accp[jj][3] = fma2(wd[jj], a23.y, accp[jj][3]);
        }
    }

    float acc[4][8];
    #pragma unroll
    for (int jj = 0; jj < 4; jj++) {
        #pragma unroll
        for (int pr = 0; pr < 4; pr++) {
            float2 f = unp2(accp[jj][pr]);
            acc[jj][pr * 2] = f.x; acc[jj][pr * 2 + 1] = f.y;
        }
    }

    const int jg0 = oc * 128 + og * 4;
    const int pixb = pix0 + pg * 8;
    const int bb = pixb >> 12, lb = pixb & 4095;
    if (jg0 + 3 < DIN) {
        #pragma unroll
        for (int jj = 0; jj < 4; jj++) {
            float* row = g_xm + (size_t)(bb * DIN + jg0 + jj) * LSEQ + lb;
            *(float4*)row       = make_float4(acc[jj][0], acc[jj][1], acc[jj][2], acc[jj][3]);
            *(float4*)(row + 4) = make_float4(acc[jj][4], acc[jj][5], acc[jj][6], acc[jj][7]);
        }
    } else {
        const int zc = jg0 - DIN;
        #pragma unroll
        for (int pi = 0; pi < 8; pi++) {
            float* zp = g_zs + (size_t)(pixb + pi) * DIN + zc;
            *(float4*)zp = make_float4(silu_f(acc[0][pi]), silu_f(acc[1][pi]),
                                       silu_f(acc[2][pi]), silu_f(acc[3][pi]));
        }
    }
}

// ================= K2: depthwise conv + silu =================
__global__ void k2_conv(const float* __restrict__ cw, const float* __restrict__ cb)
{
    __shared__ float tin [64 * 65];
    __shared__ float tout[64 * 65];
    const int tid = threadIdx.x;
    const int bd = blockIdx.x;
    const int d = bd % DIN;
    const float* src = g_xm + (size_t)bd * LSEQ;

    for (int t = tid; t < 1024; t += 256) {
        float4 v = ((const float4*)src)[t];
        int i = t * 4;
        int h = i >> 6, w = i & 63;
        float* p = &tin[h * 65 + w];
        p[0] = v.x; p[1] = v.y; p[2] = v.z; p[3] = v.w;
    }
    float wreg[9];
    #pragma unroll
    for (int i = 0; i < 9; i++) wreg[i] = cw[d * 9 + i];
    const float bias = cb[d];
    __syncthreads();

    float* dst0 = g_x0 + (size_t)bd * LSEQ;
    for (int t = tid; t < 4096; t += 256) {
        int h = t >> 6, w = t & 63;
        float acc = bias;
        #pragma unroll
        for (int dy = 0; dy < 3; dy++) {
            int hh = h + dy - 1;
            if (hh < 0 || hh > 63) continue;
            #pragma unroll
            for (int dx = 0; dx < 3; dx++) {
                int ww = w + dx - 1;
                if (ww < 0 || ww > 63) continue;
                acc = fmaf(tin[hh * 65 + ww], wreg[dy * 3 + dx], acc);
            }
        }
        float v = silu_f(acc);
        dst0[t] = v;
        tout[h * 65 + w] = v;
    }
    __syncthreads();

    float* dst1 = g_x1 + (size_t)bd * LSEQ;
    for (int t = tid; t < 4096; t += 256) {
        int w = t >> 6, h = t & 63;
        dst1[t] = tout[h * 65 + w];
    }
}

// ================= K3: x_proj + dt_proj + softplus =================
__global__ void __launch_bounds__(256, 4) k3_xproj(const float* __restrict__ xpw,
                                                   const float* __restrict__ dtw,
                                                   const float* __restrict__ dtb)
{
    extern __shared__ float sm[];
    float* wp_t = sm;                         // 192*48
    float* xd_s = wp_t + 192 * 48;            // 38*65
    float* dw_s = xd_s + 38 * 65;             // 192*6
    float* db_s = dw_s + 192 * 6;             // 192
    const int tid = threadIdx.x;
    const int bk = blockIdx.x >> 6;
    const int b = bk >> 2, k = bk & 3;
    const int l0 = (blockIdx.x & 63) << 6;
    const float* seq = (k & 1) ? g_x1 : g_x0;

    for (int i = tid; i < 192 * 48; i += 256) wp_t[i] = 0.f;
    __syncthreads();

    for (int i = tid; i < 38 * 192; i += 256) {
        int kk = i % 192, row = i / 192;
        wp_t[kk * 48 + row] = xpw[k * 38 * 192 + i];
    }
    for (int i = tid; i < 192 * 6;  i += 256) dw_s[i] = dtw[k * 192 * 6 + i];
    for (int i = tid; i < 192;      i += 256) db_s[i] = dtb[k * DIN + i];
    __syncthreads();

    const int col = tid & 63, grp = tid >> 6;
    const float* up = seq + (size_t)b * DIN * LSEQ + l0 + col;
    u64 accp[6];
    #pragma unroll
    for (int j = 0; j < 6; j++) accp[j] = 0ull;
    #pragma unroll 4
    for (int kk = 0; kk < 192; kk++) {
        float uv = __ldg(up + (size_t)kk * LSEQ);
        u64 ud = dup2(uv);
        const ulonglong2* wp2 = (const ulonglong2*)(wp_t + kk * 48 + grp * 12);
        ulonglong2 wA = wp2[0], wB = wp2[1], wC = wp2[2];
        accp[0] = fma2(wA.x, ud, accp[0]);
        accp[1] = fma2(wA.y, ud, accp[1]);
        accp[2] = fma2(wB.x, ud, accp[2]);
        accp[3] = fma2(wB.y, ud, accp[3]);
        accp[4] = fma2(wC.x, ud, accp[4]);
        accp[5] = fma2(wC.y, ud, accp[5]);
    }
    #pragma unroll
    for (int j = 0; j < 6; j++) {
        float2 f = unp2(accp[j]);
        int row0 = grp * 12 + j * 2;
        if (row0 < 38)     xd_s[row0 * 65 + col] = f.x;
        if (row0 + 1 < 38) xd_s[(row0 + 1) * 65 + col] = f.y;
    }
    __syncthreads();

    const size_t lb4 = (size_t)bk * 1024 + (l0 >> 2);
    for (int i = tid; i < 16 * 64; i += 256) {
        int n = i & 15, cc = i >> 4;
        ((float*)g_bb4)[((lb4 + (cc >> 2)) * 16 + n) * 4 + (cc & 3)] = xd_s[(6 + n) * 65 + cc];
    }
    const size_t bcbase = (size_t)bk * LSEQ + l0;
    for (int i = tid; i < 8 * 64; i += 256) {
        int n8 = i & 7, cc = i >> 3;
        float4 v;
        v.x = xd_s[(6  + n8) * 65 + cc];
        v.y = xd_s[(22 + n8) * 65 + cc];
        v.z = xd_s[(14 + n8) * 65 + cc];
        v.w = xd_s[(30 + n8) * 65 + cc];
        g_bc4[(bcbase + cc) * 8 + n8] = v;
    }
    float xdv[6];
    #pragma unroll
    for (int r = 0; r < 6; r++) xdv[r] = xd_s[r * 65 + col];
    const int dg = tid >> 6;
    const size_t dbase = (size_t)bk * DIN * LSEQ;
    for (int j = 0; j < 48; j++) {
        int d = dg + 4 * j;
        float val = db_s[d];
        #pragma unroll
        for (int r = 0; r < 6; r++)
            val = fmaf(dw_s[d * 6 + r], xdv[r], val);
        float t = fexp(-fabsf(val));
        val = fmaxf(val, 0.f) + lg2(1.f + t) * 0.69314718f;
        g_delta[dbase + (size_t)d * LSEQ + l0 + col] = val;
    }
}

// ================= K4a: local chunk scan (NCHUNK=32) =================
template<bool REV>
__device__ __forceinline__ void k4a_body(const int K0, const float* __restrict__ alog,
                                         float4* sB)
{
    const int tid = threadIdx.x;
    const int lane = tid & 31, wi = tid >> 5;
    int bx = blockIdx.x;
    const int pb = bx % 12; bx /= 12;
    const int chunk = bx & 31; bx >>= 5;
    const int kk = bx & 1;
    const int b  = bx >> 1;
    const int p = pb * 8 + wi;
    const int half = lane >> 4, n = lane & 15;
    const int d = p * 2 + half;
    const int k = K0 + kk;
    const int bk = b * 4 + k;
    const int ch = bk * DIN + d;
    const float An2 = -fexp(alog[(k * DIN + d) * NST + n]) * 1.44269504f;
    const u64 An2d = dup2(An2);

    {
        const int tb = REV ? (1024 - (chunk + 1) * 32) : chunk * 32;
        const float4* src = g_bb4 + ((size_t)bk * 1024 + tb) * 16;
        #pragma unroll
        for (int i = 0; i < 2; i++) sB[tid + i * 256] = src[tid + i * 256];
    }
    __syncthreads();

    const float* dptr = g_delta + ((size_t)bk * DIN + d) * LSEQ;
    const float* uptr = (kk ? g_x1 : g_x0) + ((size_t)b * DIN + d) * LSEQ;

    float h = 0.f;
    u64 sdel2 = 0ull;
    if (!REV) {
        const int i0 = chunk * CLEN;
        const ulonglong2* dp2 = (const ulonglong2*)(dptr + i0);
        const ulonglong2* up2 = (const ulonglong2*)(uptr + i0);
        #pragma unroll 4
        for (int s = 0; s < CLEN / 4; s++) {
            ulonglong2 dp = dp2[s], up = up2[s];
            float4 b4 = sB[s * 16 + n];
            u64 e01  = mul2(dp.x, An2d), e23  = mul2(dp.y, An2d);
            u64 du01 = mul2(dp.x, up.x), du23 = mul2(dp.y, up.y);
            sdel2 = add2(sdel2, dp.x); sdel2 = add2(sdel2, dp.y);
            float2 e0 = unp2(e01), e2 = unp2(e23);
            float2 dA = unp2(du01), dB = unp2(du23);
            h = fmaf(ex2(e0.x), h, dA.x * b4.x);
            h = fmaf(ex2(e0.y), h, dA.y * b4.y);
            h = fmaf(ex2(e2.x), h, dB.x * b4.z);
            h = fmaf(ex2(e2.y), h, dB.y * b4.w);
        }
    } else {
        const int ltop = LSEQ - chunk * CLEN;
        const ulonglong2* dp2 = (const ulonglong2*)(dptr + ltop) - 1;
        const ulonglong2* up2 = (const ulonglong2*)(uptr + ltop) - 1;
        #pragma unroll 4
        for (int s = 0; s < CLEN / 4; s++) {
            ulonglong2 dp = dp2[-s], up = up2[-s];
            float4 b4 = sB[(CLEN / 4 - 1 - s) * 16 + n];
            u64 e01  = mul2(dp.x, An2d), e23  = mul2(dp.y, An2d);
            u64 du01 = mul2(dp.x, up.x), du23 = mul2(dp.y, up.y);
            sdel2 = add2(sdel2, dp.x); sdel2 = add2(sdel2, dp.y);
            float2 e0 = unp2(e01), e2 = unp2(e23);
            float2 dA = unp2(du01), dB = unp2(du23);
            h = fmaf(ex2(e2.y), h, dB.y * b4.w);
            h = fmaf(ex2(e2.x), h, dB.x * b4.z);
            h = fmaf(ex2(e0.y), h, dA.y * b4.y);
            h = fmaf(ex2(e0.x), h, dA.x * b4.x);
        }
    }
    float2 sd = unp2(sdel2);
    g_P [(ch * NCHUNK + chunk) * NST + n] = ex2(An2 * (sd.x + sd.y));
    g_he[(ch * NCHUNK + chunk) * NST + n] = h;
}

__global__ void __launch_bounds__(256, 6) k4a_scan(const float* __restrict__ alog)
{
    __shared__ float4 sB[512];
    if (blockIdx.y == 0) k4a_body<false>(0, alog, sB);
    else                 k4a_body<true >(2, alog, sB);
}

// ================= K4b: carry across chunks =================
__global__ void k4b_carry()
{
    int idx = blockIdx.x * 256 + threadIdx.x;
    int ch = idx >> 4, n = idx & 15;
    float H = 0.f;
    #pragma unroll
    for (int c = 0; c < NCHUNK; c++) {
        int o = (ch * NCHUNK + c) * NST + n;
        g_H[o] = H;
        H = fmaf(g_P[o], H, g_he[o]);
    }
}

// ================= K4c: seeded scan, emit y (gu under store predicate) =========
template<bool REV>
__device__ __forceinline__ void k4c_body(const int K0, const float* __restrict__ alog,
                                         const float* __restrict__ ds, float4* sBC)
{
    const int tid = threadIdx.x;
    const int lane = tid & 31, wi = tid >> 5;
    int bx = blockIdx.x;
    const int qb = bx % 6; bx /= 6;
    const int chunk = bx & 31; bx >>= 5;
    const int kk = bx & 1;
    const int b  = bx >> 1;
    const int q = qb * 8 + wi;
    const int c2 = lane >> 3;
    const int n0 = lane & 7;
    const int d = q * 4 + c2;
    const int k = K0 + kk;
    const int bk = b * 4 + k;
    const int ch = bk * DIN + d;

    {
        const int lt0 = REV ? (LSEQ - (chunk + 1) * CLEN) : chunk * CLEN;
        const float4* src = g_bc4 + ((size_t)bk * LSEQ + lt0) * 8;
        #pragma unroll
        for (int i = 0; i < 4; i++) sBC[tid + i * 256] = src[tid + i * 256];
    }
    __syncthreads();

    const float An0 = -fexp(alog[(k * DIN + d) * NST + n0]) * 1.44269504f;
    const float An1 = -fexp(alog[(k * DIN + d) * NST + n0 + 8]) * 1.44269504f;
    const u64 An0d = dup2(An0), An1d = dup2(An1);
    const float Dd = ds[k * DIN + d];
    const u64 Ddd = dup2(Dd);

    const float* dptr = g_delta + ((size_t)bk * DIN + d) * LSEQ;
    const float* uptr = (kk ? g_x1 : g_x0) + ((size_t)b * DIN + d) * LSEQ;
    float* yp = g_y + ((size_t)(k * BATCH + b) * DIN + d) * LSEQ;

    float h0 = g_H[(ch * NCHUNK + chunk) * NST + n0];
    float h1 = g_H[(ch * NCHUNK + chunk) * NST + n0 + 8];

    if (!REV) {
        const int i0 = chunk * CLEN;
        const ulonglong2* dp2 = (const ulonglong2*)(dptr + i0);
        const ulonglong2* up2 = (const ulonglong2*)(uptr + i0);
        float4* yp4 = (float4*)(yp + i0);
        #pragma unroll 4
        for (int s = 0; s < CLEN / 4; s++) {
            ulonglong2 dp = dp2[s], up = up2[s];
            u64 eA01 = mul2(dp.x, An0d), eA23 = mul2(dp.y, An0d);
            u64 eB01 = mul2(dp.x, An1d), eB23 = mul2(dp.y, An1d);
            u64 du01 = mul2(dp.x, up.x), du23 = mul2(dp.y, up.y);
            float2 eA0 = unp2(eA01), eA2 = unp2(eA23);
            float2 eB0 = unp2(eB01), eB2 = unp2(eB23);
            float2 duA = unp2(du01), duB = unp2(du23);
            float eAj[4] = {eA0.x, eA0.y, eA2.x, eA2.y};
            float eBj[4] = {eB0.x, eB0.y, eB2.x, eB2.y};
            float duj[4] = {duA.x, duA.y, duB.x, duB.y};
            float tr[4];
            #pragma unroll
            for (int j = 0; j < 4; j++) {
                float4 bc = sBC[(s * 4 + j) * 8 + n0];
                h0 = fmaf(ex2(eAj[j]), h0, duj[j] * bc.x);
                h1 = fmaf(ex2(eBj[j]), h1, duj[j] * bc.z);
                float t = fmaf(h1, bc.w, h0 * bc.y);
                t += __shfl_xor_sync(0xffffffffu, t, 4);
                t += __shfl_xor_sync(0xffffffffu, t, 2);
                t += __shfl_xor_sync(0xffffffffu, t, 1);
                tr[j] = t;
            }
            if (n0 == 0) {
                u64 gux = mul2(up.x, Ddd), guy = mul2(up.y, Ddd);
                float2 g0 = unp2(gux), g1 = unp2(guy);
                yp4[s] = make_float4(tr[0] + g0.x, tr[1] + g0.y,
                                     tr[2] + g1.x, tr[3] + g1.y);
            }
        }
    } else {
        const int ltop = LSEQ - chunk * CLEN;
        const ulonglong2* dp2 = (const ulonglong2*)(dptr + ltop) - 1;
        const ulonglong2* up2 = (const ulonglong2*)(uptr + ltop) - 1;
        float4* yp4 = (float4*)(yp + ltop) - 1;
        #pragma unroll 4
        for (int s = 0; s < CLEN / 4; s++) {
            ulonglong2 dp = dp2[-s], up = up2[-s];
            u64 eA01 = mul2(dp.x, An0d), eA23 = mul2(dp.y, An0d);
            u64 eB01 = mul2(dp.x, An1d), eB23 = mul2(dp.y, An1d);
            u64 du01 = mul2(dp.x, up.x), du23 = mul2(dp.y, up.y);
            float2 eA0 = unp2(eA01), eA2 = unp2(eA23);
            float2 eB0 = unp2(eB01), eB2 = unp2(eB23);
            float2 duA = unp2(du01), duB = unp2(du23);
            float eAj[4] = {eA0.x, eA0.y, eA2.x, eA2.y};
            float eBj[4] = {eB0.x, eB0.y, eB2.x, eB2.y};
            float duj[4] = {duA.x, duA.y, duB.x, duB.y};
            float tr[4];
            #pragma unroll
            for (int j = 3; j >= 0; j--) {
                float4 bc = sBC[(CLEN - 1 - (s * 4 + (3 - j))) * 8 + n0];
                h0 = fmaf(ex2(eAj[j]), h0, duj[j] * bc.x);
                h1 = fmaf(ex2(eBj[j]), h1, duj[j] * bc.z);
                float t = fmaf(h1, bc.w, h0 * bc.y);
                t += __shfl_xor_sync(0xffffffffu, t, 4);
                t += __shfl_xor_sync(0xffffffffu, t, 2);
                t += __shfl_xor_sync(0xffffffffu, t, 1);
                tr[j] = t;
            }
            if (n0 == 0) {
                u64 gux = mul2(up.x, Ddd), guy = mul2(up.y, Ddd);
                float2 g0 = unp2(gux), g1 = unp2(guy);
                yp4[-s] = make_float4(tr[0] + g0.x, tr[1] + g0.y,
                                      tr[2] + g1.x, tr[3] + g1.y);
            }
        }
    }
}

__global__ void __launch_bounds__(256, 6) k4c_scan(const float* __restrict__ alog,
                                                   const float* __restrict__ ds)
{
    __shared__ float4 sBC[1024];
    if (blockIdx.y == 0) k4c_body<false>(0, alog, ds, sBC);
    else                 k4c_body<true >(2, alog, ds, sBC);
}

// ================= K4t: transpose wh planes + merge all 4 into g_ysum =========
__global__ void k4t_merge()
{
    __shared__ float s1[64 * 65];
    __shared__ float s3[64 * 65];
    const int tid = threadIdx.x;
    const int b = blockIdx.x / DIN;
    const int d = blockIdx.x % DIN;
    const float4* p0 = (const float4*)(g_y + ((size_t)(0 * BATCH + b) * DIN + d) * LSEQ);
    const float4* p1 = (const float4*)(g_y + ((size_t)(1 * BATCH + b) * DIN + d) * LSEQ);
    const float4* p2 = (const float4*)(g_y + ((size_t)(2 * BATCH + b) * DIN + d) * LSEQ);
    const float4* p3 = (const float4*)(g_y + ((size_t)(3 * BATCH + b) * DIN + d) * LSEQ);

    for (int t4 = tid; t4 < 1024; t4 += 256) {
        int i = t4 * 4;
        int w_ = i >> 6, h0 = i & 63;
        float4 v1 = p1[t4], v3 = p3[t4];
        s1[(h0 + 0) * 65 + w_] = v1.x; s1[(h0 + 1) * 65 + w_] = v1.y;
        s1[(h0 + 2) * 65 + w_] = v1.z; s1[(h0 + 3) * 65 + w_] = v1.w;
        s3[(h0 + 0) * 65 + w_] = v3.x; s3[(h0 + 1) * 65 + w_] = v3.y;
        s3[(h0 + 2) * 65 + w_] = v3.z; s3[(h0 + 3) * 65 + w_] = v3.w;
    }
    __syncthreads();

    float4* po = (float4*)(g_ysum + (size_t)(b * DIN + d) * LSEQ);
    for (int t4 = tid; t4 < 1024; t4 += 256) {
        int j = t4 * 4;
        int h = j >> 6, w0 = j & 63;
        float4 a = p0[t4], c = p2[t4];
        float4 r;
        r.x = a.x + c.x + s1[h * 65 + w0 + 0] + s3[h * 65 + w0 + 0];
        r.y = a.y + c.y + s1[h * 65 + w0 + 1] + s3[h * 65 + w0 + 1];
        r.z = a.z + c.z + s1[h * 65 + w0 + 2] + s3[h * 65 + w0 + 2];
        r.w = a.w + c.w + s1[h * 65 + w0 + 3] + s3[h * 65 + w0 + 3];
        po[t4] = r;
    }
}

// ================= K5: out-LN + gate + out_proj + residual (16 px/block) =======
__global__ void __launch_bounds__(256, 8) k5_final(const float* __restrict__ onw,
                                                   const float* __restrict__ onb,
                                                   const float* __restrict__ wout,
                                                   float* __restrict__ out)
{
    extern __shared__ float sm[];
    float* yc = sm;                  // 192*20 (padded)
    const int tid = threadIdx.x, lane = tid & 31, warp = tid >> 5;
    const int b = blockIdx.x >> 8;
    const int l0 = (blockIdx.x & 255) << 4;

    for (int i = tid; i < 192 * 16; i += 256) {
        int d = i >> 4, p = i & 15;
        yc[d * 20 + p] = g_ysum[(size_t)(b * DIN + d) * LSEQ + l0 + p];
    }
    __syncthreads();

    #pragma unroll
    for (int pp = 0; pp < 2; pp++) {
        const int p = warp * 2 + pp;
        float s = 0.f, s2 = 0.f, vv[6];
        #pragma unroll
        for (int j = 0; j < 6; j++) {
            float v = yc[(lane + 32 * j) * 20 + p];
            vv[j] = v; s += v; s2 += v * v;
        }
        #pragma unroll
        for (int o = 16; o > 0; o >>= 1) {
            s  += __shfl_xor_sync(0xffffffffu, s,  o);
            s2 += __shfl_xor_sync(0xffffffffu, s2, o);
        }
        float mu = s * (1.f / 192.f);
        float var = s2 * (1.f / 192.f) - mu * mu;
        float rstd = rsqrtf(var + 1e-5f);
        size_t zbase = ((size_t)(b * LSEQ + l0 + p)) * DIN;
        #pragma unroll
        for (int j = 0; j < 6; j++) {
            int dd = lane + 32 * j;
            float g = (vv[j] - mu) * rstd * onw[dd] + onb[dd];
            yc[dd * 20 + p] = g * g_zs[zbase + dd];
        }
    }
    __syncthreads();

    const int og = tid >> 3;
    const int pg = tid & 7;
    u64 accp[3];
    accp[0] = accp[1] = accp[2] = 0ull;

    for (int dd4 = 0; dd4 < 192; dd4 += 4) {
        float4 w0 = __ldg((const float4*)(wout + (og * 3 + 0) * 192 + dd4));
        float4 w1 = __ldg((const float4*)(wout + (og * 3 + 1) * 192 + dd4));
        float4 w2 = __ldg((const float4*)(wout + (og * 3 + 2) * 192 + dd4));
        float w0a[4] = {w0.x, w0.y, w0.z, w0.w};
        float w1a[4] = {w1.x, w1.y, w1.z, w1.w};
        float w2a[4] = {w2.x, w2.y, w2.z, w2.w};
        #pragma unroll
        for (int j = 0; j < 4; j++) {
            u64 g = *(const u64*)&yc[(dd4 + j) * 20 + pg * 2];
            accp[0] = fma2(dup2(w0a[j]), g, accp[0]);
            accp[1] = fma2(dup2(w1a[j]), g, accp[1]);
            accp[2] = fma2(dup2(w2a[j]), g, accp[2]);
        }
    }
    __syncthreads();

    float* buf = sm;                 // 16 x 100 staging
    #pragma unroll
    for (int oi = 0; oi < 3; oi++) {
        float2 f = unp2(accp[oi]);
        buf[(pg * 2 + 0) * 100 + og * 3 + oi] = f.x;
        buf[(pg * 2 + 1) * 100 + og * 3 + oi] = f.y;
    }
    __syncthreads();

    const float4* df4 = (const float4*)(g_diff + ((size_t)b * LSEQ + l0) * CDIM);
    float4* out4 = (float4*)(out + ((size_t)b * LSEQ + l0) * CDIM);
    for (int t = tid; t < 16 * 24; t += 256) {
        int p = t / 24, o4 = t % 24;
        float4 v = *(const float4*)&buf[p * 100 + o4 * 4];
        float4 dv = df4[p * 24 + o4];
        v.x += dv.x; v.y += dv.y; v.z += dv.z; v.w += dv.w;
        out4[p * 24 + o4] = v;
    }
}

// ================= launch =================
extern "C" void kernel_launch(void* const* d_in, const int* in_sizes, int n_in,
                              void* d_out, int out_size)
{
    const float* x     = (const float*)d_in[0];
    const float* y     = (const float*)d_in[1];
    const float* ln_w  = (const float*)d_in[2];
    const float* ln_b  = (const float*)d_in[3];
    const float* ipw   = (const float*)d_in[4];
    const float* cw    = (const float*)d_in[5];
    const float* cb    = (const float*)d_in[6];
    const float* xpw   = (const float*)d_in[7];
    const float* dtw   = (const float*)d_in[8];
    const float* dtb   = (const float*)d_in[9];
    const float* alog  = (const float*)d_in[10];
    const float* ds    = (const float*)d_in[11];
    const float* onw   = (const float*)d_in[12];
    const float* onb   = (const float*)d_in[13];
    const float* wout  = (const float*)d_in[14];
    float* out = (float*)d_out;

    const int smem1 = (96 * 64 + 96 * 128) * 4;
    const int smem3 = (192 * 48 + 38 * 65 + 192 * 6 + 192) * 4;
    const int smem5 = (192 * 20) * 4;
    cudaFuncSetAttribute(k1_prologue, cudaFuncAttributeMaxDynamicSharedMemorySize, smem1);
    cudaFuncSetAttribute(k3_xproj,   cudaFuncAttributeMaxDynamicSharedMemorySize, smem3);
    cudaFuncSetAttribute(k5_final,   cudaFuncAttributeMaxDynamicSharedMemorySize, smem5);

    k1_prologue<<<dim3(128, 3), 256, smem1>>>(x, y, ln_w, ln_b, ipw);
    k2_conv<<<BATCH * DIN, 256>>>(cw, cb);
    k3_xproj<<<BATCH * 4 * (LSEQ / 64), 256, smem3>>>(xpw, dtw, dtb);
    k4a_scan<<<dim3(1536, 2), 256>>>(alog);
    k4b_carry<<<NCH * NST / 256, 256>>>();
    k4c_scan<<<dim3(768, 2), 256>>>(alog, ds);
    k4t_merge<<<BATCH * DIN, 256>>>();
    k5_final<<<BATCH * (LSEQ / 16), 256, smem5>>>(onw, onb, wout, out);
}

// round 16
// speedup vs baseline: 1.1071x; 1.0285x over previous
#include <cuda_runtime.h>
#include <math.h>

#define BATCH 2
#define CDIM  96
#define DIN   192
#define NST   16
#define LSEQ  4096
#define NPIX  (BATCH*LSEQ)
#define NCH   (BATCH*4*DIN)
#define NCHUNK 32
#define CLEN  (LSEQ/NCHUNK)     // 128

typedef unsigned long long u64;

// ---------------- persistent device scratch ----------------
__device__ float  g_diff [NPIX*CDIM];
__device__ float  g_zs   [NPIX*DIN];
__device__ float  g_xm   [BATCH*DIN*LSEQ];
__device__ float  g_x0   [BATCH*DIN*LSEQ];
__device__ float  g_x1   [BATCH*DIN*LSEQ];
__device__ float  g_delta[BATCH*4*DIN*LSEQ];
__device__ float4 g_bb4  [BATCH*4*(LSEQ/4)*16];
__device__ float4 g_bc4  [BATCH*4*LSEQ*8];
__device__ float  g_y    [4*BATCH*DIN*LSEQ];
__device__ float  g_ysum [BATCH*DIN*LSEQ];
__device__ float  g_P    [NCH*NCHUNK*NST];
__device__ float  g_he   [NCH*NCHUNK*NST];
__device__ float  g_H    [NCH*NCHUNK*NST];

// ---- fast intrinsics ----
__device__ __forceinline__ float ex2(float x){ float r; asm("ex2.approx.f32 %0, %1;" : "=f"(r) : "f"(x)); return r; }
__device__ __forceinline__ float lg2(float x){ float r; asm("lg2.approx.f32 %0, %1;" : "=f"(r) : "f"(x)); return r; }
__device__ __forceinline__ float fexp(float x){ return ex2(x * 1.44269504f); }
__device__ __forceinline__ float silu_f(float v){ return v / (1.f + fexp(-v)); }

// ---- packed fp32x2 helpers (sm_103a) ----
__device__ __forceinline__ u64 dup2(float v) {
    u64 r; asm("mov.b64 %0, {%1, %1};" : "=l"(r) : "f"(v)); return r;
}
__device__ __forceinline__ u64 pk2(float a, float b) {
    u64 r; asm("mov.b64 %0, {%1, %2};" : "=l"(r) : "f"(a), "f"(b)); return r;
}
__device__ __forceinline__ u64 fma2(u64 a, u64 b, u64 c) {
    u64 d; asm("fma.rn.f32x2 %0, %1, %2, %3;" : "=l"(d) : "l"(a), "l"(b), "l"(c)); return d;
}
__device__ __forceinline__ u64 mul2(u64 a, u64 b) {
    u64 d; asm("mul.rn.f32x2 %0, %1, %2;" : "=l"(d) : "l"(a), "l"(b)); return d;
}
__device__ __forceinline__ u64 add2(u64 a, u64 b) {
    u64 d; asm("add.rn.f32x2 %0, %1, %2;" : "=l"(d) : "l"(a), "l"(b)); return d;
}
__device__ __forceinline__ float2 unp2(u64 v) {
    float2 r; asm("mov.b64 {%0, %1}, %2;" : "=f"(r.x), "=f"(r.y) : "l"(v)); return r;
}

// ================= K1: diff + LN + in_proj GEMM (f32x2) =================
__global__ void k1_prologue(const float* __restrict__ x, const float* __restrict__ y,
                            const float* __restrict__ lnw, const float* __restrict__ lnb,
                            const float* __restrict__ wproj)
{
    extern __shared__ float sm[];
    float* A_s = sm;            // 96*64
    float* W_s = sm + 96*64;    // 96*128
    const int tid = threadIdx.x, lane = tid & 31, warp = tid >> 5;
    const int pix0 = blockIdx.x * 64;
    const int oc = blockIdx.y;

    for (int pp = 0; pp < 8; pp++) {
        const int p = warp * 8 + pp;
        const int base = (pix0 + p) * CDIM;
        float vv[3]; float s = 0.f, s2 = 0.f;
        #pragma unroll
        for (int j = 0; j < 3; j++) {
            int ch = lane + 32 * j;
            float d = fabsf(x[base + ch] - y[base + ch]);
            if (oc == 0) g_diff[base + ch] = d;
            vv[j] = d; s += d; s2 += d * d;
        }
        #pragma unroll
        for (int o = 16; o > 0; o >>= 1) {
            s  += __shfl_xor_sync(0xffffffffu, s,  o);
            s2 += __shfl_xor_sync(0xffffffffu, s2, o);
        }
        float mu = s * (1.f / 96.f);
        float var = s2 * (1.f / 96.f) - mu * mu;
        float rstd = rsqrtf(var + 1e-5f);
        #pragma unroll
        for (int j = 0; j < 3; j++) {
            int ch = lane + 32 * j;
            A_s[ch * 64 + p] = (vv[j] - mu) * rstd * lnw[ch] + lnb[ch];
        }
    }
    for (int i = tid; i < 96 * 128; i += 256) {
        int kk = i % 96, j = i / 96;
        W_s[kk * 128 + j] = wproj[(oc * 128 + j) * 96 + kk];
    }
    __syncthreads();

    const int pg = tid & 7;
    const int og = tid >> 3;
    const float4* W4 = (const float4*)W_s;

    u64 accp[4][4];
    #pragma unroll
    for (int a = 0; a < 4; a++)
        #pragma unroll
        for (int b = 0; b < 4; b++) accp[a][b] = 0ull;

    #pragma unroll 4
    for (int kk = 0; kk < 96; kk++) {
        const ulonglong2* ap = (const ulonglong2*)(A_s + kk * 64 + pg * 8);
        ulonglong2 a01 = ap[0], a23 = ap[1];
        float4 w = W4[kk * 32 + og];
        u64 wd[4] = {dup2(w.x), dup2(w.y), dup2(w.z), dup2(w.w)};
        #pragma unroll
        for (int jj = 0; jj < 4; jj++) {
            accp[jj][0] = fma2(wd[jj], a01.x, accp[jj][0]);
            accp[jj][1] = fma2(wd[jj], a01.y, accp[jj][1]);
            accp[jj][2] = fma2(wd[jj], a23.x, accp[jj][2]);
            accp[jj][3] = fma2(wd[jj], a23.y, accp[jj][3]);
        }
    }

    float acc[4][8];
    #pragma unroll
    for (int jj = 0; jj < 4; jj++) {
        #pragma unroll
        for (int pr = 0; pr < 4; pr++) {
            float2 f = unp2(accp[jj][pr]);
            acc[jj][pr * 2] = f.x; acc[jj][pr * 2 + 1] = f.y;
        }
    }

    const int jg0 = oc * 128 + og * 4;
    const int pixb = pix0 + pg * 8;
    const int bb = pixb >> 12, lb = pixb & 4095;
    if (jg0 + 3 < DIN) {
        #pragma unroll
        for (int jj = 0; jj < 4; jj++) {
            float* row = g_xm + (size_t)(bb * DIN + jg0 + jj) * LSEQ + lb;
            *(float4*)row       = make_float4(acc[jj][0], acc[jj][1], acc[jj][2], acc[jj][3]);
            *(float4*)(row + 4) = make_float4(acc[jj][4], acc[jj][5], acc[jj][6], acc[jj][7]);
        }
    } else {
        const int zc = jg0 - DIN;
        #pragma unroll
        for (int pi = 0; pi < 8; pi++) {
            float* zp = g_zs + (size_t)(pixb + pi) * DIN + zc;
            *(float4*)zp = make_float4(silu_f(acc[0][pi]), silu_f(acc[1][pi]),
                                       silu_f(acc[2][pi]), silu_f(acc[3][pi]));
        }
    }
}

// ================= K2: depthwise conv + silu =================
__global__ void k2_conv(const float* __restrict__ cw, const float* __restrict__ cb)
{
    __shared__ float tin [64 * 65];
    __shared__ float tout[64 * 65];
    const int tid = threadIdx.x;
    const int bd = blockIdx.x;
    const int d = bd % DIN;
    const float* src = g_xm + (size_t)bd * LSEQ;

    for (int t = tid; t < 1024; t += 256) {
        float4 v = ((const float4*)src)[t];
        int i = t * 4;
        int h = i >> 6, w = i & 63;
        float* p = &tin[h * 65 + w];
        p[0] = v.x; p[1] = v.y; p[2] = v.z; p[3] = v.w;
    }
    float wreg[9];
    #pragma unroll
    for (int i = 0; i < 9; i++) wreg[i] = cw[d * 9 + i];
    const float bias = cb[d];
    __syncthreads();

    float* dst0 = g_x0 + (size_t)bd * LSEQ;
    for (int t = tid; t < 4096; t += 256) {
        int h = t >> 6, w = t & 63;
        float acc = bias;
        #pragma unroll
        for (int dy = 0; dy < 3; dy++) {
            int hh = h + dy - 1;
            if (hh < 0 || hh > 63) continue;
            #pragma unroll
            for (int dx = 0; dx < 3; dx++) {
                int ww = w + dx - 1;
                if (ww < 0 || ww > 63) continue;
                acc = fmaf(tin[hh * 65 + ww], wreg[dy * 3 + dx], acc);
            }
        }
        float v = silu_f(acc);
        dst0[t] = v;
        tout[h * 65 + w] = v;
    }
    __syncthreads();

    float* dst1 = g_x1 + (size_t)bd * LSEQ;
    for (int t = tid; t < 4096; t += 256) {
        int w = t >> 6, h = t & 63;
        dst1[t] = tout[h * 65 + w];
    }
}

// ================= K3: x_proj + dt_proj + softplus =================
__global__ void __launch_bounds__(256, 4) k3_xproj(const float* __restrict__ xpw,
                                                   const float* __restrict__ dtw,
                                                   const float* __restrict__ dtb)
{
    extern __shared__ float sm[];
    float* wp_t = sm;                         // 192*48
    float* xd_s = wp_t + 192 * 48;            // 38*65
    float* dw_s = xd_s + 38 * 65;             // 192*6
    float* db_s = dw_s + 192 * 6;             // 192
    const int tid = threadIdx.x;
    const int bk = blockIdx.x >> 6;
    const int b = bk >> 2, k = bk & 3;
    const int l0 = (blockIdx.x & 63) << 6;
    const float* seq = (k & 1) ? g_x1 : g_x0;

    for (int i = tid; i < 192 * 48; i += 256) wp_t[i] = 0.f;
    __syncthreads();

    for (int i = tid; i < 38 * 192; i += 256) {
        int kk = i % 192, row = i / 192;
        wp_t[kk * 48 + row] = xpw[k * 38 * 192 + i];
    }
    for (int i = tid; i < 192 * 6;  i += 256) dw_s[i] = dtw[k * 192 * 6 + i];
    for (int i = tid; i < 192;      i += 256) db_s[i] = dtb[k * DIN + i];
    __syncthreads();

    const int col = tid & 63, grp = tid >> 6;
    const float* up = seq + (size_t)b * DIN * LSEQ + l0 + col;
    u64 accp[6];
    #pragma unroll
    for (int j = 0; j < 6; j++) accp[j] = 0ull;
    #pragma unroll 4
    for (int kk = 0; kk < 192; kk++) {
        float uv = __ldg(up + (size_t)kk * LSEQ);
        u64 ud = dup2(uv);
        const ulonglong2* wp2 = (const ulonglong2*)(wp_t + kk * 48 + grp * 12);
        ulonglong2 wA = wp2[0], wB = wp2[1], wC = wp2[2];
        accp[0] = fma2(wA.x, ud, accp[0]);
        accp[1] = fma2(wA.y, ud, accp[1]);
        accp[2] = fma2(wB.x, ud, accp[2]);
        accp[3] = fma2(wB.y, ud, accp[3]);
        accp[4] = fma2(wC.x, ud, accp[4]);
        accp[5] = fma2(wC.y, ud, accp[5]);
    }
    #pragma unroll
    for (int j = 0; j < 6; j++) {
        float2 f = unp2(accp[j]);
        int row0 = grp * 12 + j * 2;
        if (row0 < 38)     xd_s[row0 * 65 + col] = f.x;
        if (row0 + 1 < 38) xd_s[(row0 + 1) * 65 + col] = f.y;
    }
    __syncthreads();

    const size_t lb4 = (size_t)bk * 1024 + (l0 >> 2);
    for (int i = tid; i < 16 * 64; i += 256) {
        int n = i & 15, cc = i >> 4;
        ((float*)g_bb4)[((lb4 + (cc >> 2)) * 16 + n) * 4 + (cc & 3)] = xd_s[(6 + n) * 65 + cc];
    }
    const size_t bcbase = (size_t)bk * LSEQ + l0;
    for (int i = tid; i < 8 * 64; i += 256) {
        int n8 = i & 7, cc = i >> 3;
        float4 v;
        v.x = xd_s[(6  + n8) * 65 + cc];
        v.y = xd_s[(22 + n8) * 65 + cc];
        v.z = xd_s[(14 + n8) * 65 + cc];
        v.w = xd_s[(30 + n8) * 65 + cc];
        g_bc4[(bcbase + cc) * 8 + n8] = v;
    }
    float xdv[6];
    #pragma unroll
    for (int r = 0; r < 6; r++) xdv[r] = xd_s[r * 65 + col];
    const int dg = tid >> 6;
    const size_t dbase = (size_t)bk * DIN * LSEQ;
    for (int j = 0; j < 48; j++) {
        int d = dg + 4 * j;
        float val = db_s[d];
        #pragma unroll
        for (int r = 0; r < 6; r++)
            val = fmaf(dw_s[d * 6 + r], xdv[r], val);
        float t = fexp(-fabsf(val));
        val = fmaxf(val, 0.f) + lg2(1.f + t) * 0.69314718f;
        g_delta[dbase + (size_t)d * LSEQ + l0 + col] = val;
    }
}

// ================= K4a: local chunk scan (NCHUNK=32) =================
template<bool REV>
__device__ __forceinline__ void k4a_body(const int K0, const float* __restrict__ alog,
                                         float4* sB)
{
    const int tid = threadIdx.x;
    const int lane = tid & 31, wi = tid >> 5;
    int bx = blockIdx.x;
    const int pb = bx % 12; bx /= 12;
    const int chunk = bx & 31; bx >>= 5;
    const int kk = bx & 1;
    const int b  = bx >> 1;
    const int p = pb * 8 + wi;
    const int half = lane >> 4, n = lane & 15;
    const int d = p * 2 + half;
    const int k = K0 + kk;
    const int bk = b * 4 + k;
    const int ch = bk * DIN + d;
    const float An2 = -fexp(alog[(k * DIN + d) * NST + n]) * 1.44269504f;
    const u64 An2d = dup2(An2);

    {
        const int tb = REV ? (1024 - (chunk + 1) * 32) : chunk * 32;
        const float4* src = g_bb4 + ((size_t)bk * 1024 + tb) * 16;
        #pragma unroll
        for (int i = 0; i < 2; i++) sB[tid + i * 256] = src[tid + i * 256];
    }
    __syncthreads();

    const float* dptr = g_delta + ((size_t)bk * DIN + d) * LSEQ;
    const float* uptr = (kk ? g_x1 : g_x0) + ((size_t)b * DIN + d) * LSEQ;

    float h = 0.f;
    u64 sdel2 = 0ull;
    if (!REV) {
        const int i0 = chunk * CLEN;
        const ulonglong2* dp2 = (const ulonglong2*)(dptr + i0);
        const ulonglong2* up2 = (const ulonglong2*)(uptr + i0);
        #pragma unroll 4
        for (int s = 0; s < CLEN / 4; s++) {
            ulonglong2 dp = dp2[s], up = up2[s];
            float4 b4 = sB[s * 16 + n];
            u64 e01  = mul2(dp.x, An2d), e23  = mul2(dp.y, An2d);
            u64 du01 = mul2(dp.x, up.x), du23 = mul2(dp.y, up.y);
            sdel2 = add2(sdel2, dp.x); sdel2 = add2(sdel2, dp.y);
            float2 e0 = unp2(e01), e2 = unp2(e23);
            float2 dA = unp2(du01), dB = unp2(du23);
            h = fmaf(ex2(e0.x), h, dA.x * b4.x);
            h = fmaf(ex2(e0.y), h, dA.y * b4.y);
            h = fmaf(ex2(e2.x), h, dB.x * b4.z);
            h = fmaf(ex2(e2.y), h, dB.y * b4.w);
        }
    } else {
        const int ltop = LSEQ - chunk * CLEN;
        const ulonglong2* dp2 = (const ulonglong2*)(dptr + ltop) - 1;
        const ulonglong2* up2 = (const ulonglong2*)(uptr + ltop) - 1;
        #pragma unroll 4
        for (int s = 0; s < CLEN / 4; s++) {
            ulonglong2 dp = dp2[-s], up = up2[-s];
            float4 b4 = sB[(CLEN / 4 - 1 - s) * 16 + n];
            u64 e01  = mul2(dp.x, An2d), e23  = mul2(dp.y, An2d);
            u64 du01 = mul2(dp.x, up.x), du23 = mul2(dp.y, up.y);
            sdel2 = add2(sdel2, dp.x); sdel2 = add2(sdel2, dp.y);
            float2 e0 = unp2(e01), e2 = unp2(e23);
            float2 dA = unp2(du01), dB = unp2(du23);
            h = fmaf(ex2(e2.y), h, dB.y * b4.w);
            h = fmaf(ex2(e2.x), h, dB.x * b4.z);
            h = fmaf(ex2(e0.y), h, dA.y * b4.y);
            h = fmaf(ex2(e0.x), h, dA.x * b4.x);
        }
    }
    float2 sd = unp2(sdel2);
    g_P [(ch * NCHUNK + chunk) * NST + n] = ex2(An2 * (sd.x + sd.y));
    g_he[(ch * NCHUNK + chunk) * NST + n] = h;
}

__global__ void __launch_bounds__(256, 6) k4a_scan(const float* __restrict__ alog)
{
    __shared__ float4 sB[512];
    if (blockIdx.y == 0) k4a_body<false>(0, alog, sB);
    else                 k4a_body<true >(2, alog, sB);
}

// ================= K4b: carry across chunks =================
__global__ void k4b_carry()
{
    int idx = blockIdx.x * 256 + threadIdx.x;
    int ch = idx >> 4, n = idx & 15;
    float H = 0.f;
    #pragma unroll
    for (int c = 0; c < NCHUNK; c++) {
        int o = (ch * NCHUNK + c) * NST + n;
        g_H[o] = H;
        H = fmaf(g_P[o], H, g_he[o]);
    }
}

// ================= K4c: seeded scan, 8 channels/warp, 4 states/lane =========
template<bool REV>
__device__ __forceinline__ void k4c_body(const int K0, const float* __restrict__ alog,
                                         const float* __restrict__ ds, float4* sBC)
{
    const int tid = threadIdx.x;
    const int lane = tid & 31, wi = tid >> 5;
    int bx = blockIdx.x;
    const int qb = bx % 3; bx /= 3;
    const int chunk = bx & 31; bx >>= 5;
    const int kk = bx & 1;
    const int b  = bx >> 1;
    const int c2 = lane >> 2;                  // 0..7 channel within warp
    const int n0 = lane & 3;                   // states n0, n0+4, n0+8, n0+12
    const int d = (qb * 8 + wi) * 8 + c2;      // 0..191
    const int k = K0 + kk;
    const int bk = b * 4 + k;
    const int ch = bk * DIN + d;

    {
        const int lt0 = REV ? (LSEQ - (chunk + 1) * CLEN) : chunk * CLEN;
        const float4* src = g_bc4 + ((size_t)bk * LSEQ + lt0) * 8;
        #pragma unroll
        for (int i = 0; i < 4; i++) sBC[tid + i * 256] = src[tid + i * 256];
    }
    __syncthreads();

    const float* ap = alog + (k * DIN + d) * NST;
    const float An0  = -fexp(ap[n0])      * 1.44269504f;
    const float An4  = -fexp(ap[n0 + 4])  * 1.44269504f;
    const float An8  = -fexp(ap[n0 + 8])  * 1.44269504f;
    const float An12 = -fexp(ap[n0 + 12]) * 1.44269504f;
    const u64 A08  = pk2(An0, An8);
    const u64 A412 = pk2(An4, An12);
    const float Dd = ds[k * DIN + d];
    const u64 Ddd = dup2(Dd);

    const float* dptr = g_delta + ((size_t)bk * DIN + d) * LSEQ;
    const float* uptr = (kk ? g_x1 : g_x0) + ((size_t)b * DIN + d) * LSEQ;
    float* yp = g_y + ((size_t)(k * BATCH + b) * DIN + d) * LSEQ;

    const float* Hb = g_H + (size_t)(ch * NCHUNK + chunk) * NST;
    float h0  = Hb[n0];
    float h4  = Hb[n0 + 4];
    float h8  = Hb[n0 + 8];
    float h12 = Hb[n0 + 12];

    if (!REV) {
        const int i0 = chunk * CLEN;
        const ulonglong2* dp2 = (const ulonglong2*)(dptr + i0);
        const ulonglong2* up2 = (const ulonglong2*)(uptr + i0);
        float4* yp4 = (float4*)(yp + i0);
        #pragma unroll 4
        for (int s = 0; s < CLEN / 4; s++) {
            ulonglong2 dp = dp2[s], up = up2[s];
            u64 du01 = mul2(dp.x, up.x), du23 = mul2(dp.y, up.y);
            float2 d01 = unp2(dp.x), d23 = unp2(dp.y);
            float2 duA = unp2(du01), duB = unp2(du23);
            float ddj[4] = {d01.x, d01.y, d23.x, d23.y};
            float duj[4] = {duA.x, duA.y, duB.x, duB.y};
            float tr[4];
            #pragma unroll
            for (int j = 0; j < 4; j++) {
                u64 djd = dup2(ddj[j]);
                float2 eA = unp2(mul2(djd, A08));     // (dj*An0, dj*An8)
                float2 eB = unp2(mul2(djd, A412));    // (dj*An4, dj*An12)
                float4 bca = sBC[(s * 4 + j) * 8 + n0];
                float4 bcb = sBC[(s * 4 + j) * 8 + n0 + 4];
                h0  = fmaf(ex2(eA.x), h0,  duj[j] * bca.x);
                h8  = fmaf(ex2(eA.y), h8,  duj[j] * bca.z);
                h4  = fmaf(ex2(eB.x), h4,  duj[j] * bcb.x);
                h12 = fmaf(ex2(eB.y), h12, duj[j] * bcb.z);
                float t = fmaf(h12, bcb.w, fmaf(h4, bcb.y, fmaf(h8, bca.w, h0 * bca.y)));
                t += __shfl_xor_sync(0xffffffffu, t, 2);
                t += __shfl_xor_sync(0xffffffffu, t, 1);
                tr[j] = t;
            }
            if (n0 == 0) {
                u64 gux = mul2(up.x, Ddd), guy = mul2(up.y, Ddd);
                float2 g0 = unp2(gux), g1 = unp2(guy);
                yp4[s] = make_float4(tr[0] + g0.x, tr[1] + g0.y,
                                     tr[2] + g1.x, tr[3] + g1.y);
            }
        }
    } else {
        const int ltop = LSEQ - chunk * CLEN;
        const ulonglong2* dp2 = (const ulonglong2*)(dptr + ltop) - 1;
        const ulonglong2* up2 = (const ulonglong2*)(uptr + ltop) - 1;
        float4* yp4 = (float4*)(yp + ltop) - 1;
        #pragma unroll 4
        for (int s = 0; s < CLEN / 4; s++) {
            ulonglong2 dp = dp2[-s], up = up2[-s];
            u64 du01 = mul2(dp.x, up.x), du23 = mul2(dp.y, up.y);
            float2 d01 = unp2(dp.x), d23 = unp2(dp.y);
            float2 duA = unp2(du01), duB = unp2(du23);
            float ddj[4] = {d01.x, d01.y, d23.x, d23.y};
            float duj[4] = {duA.x, duA.y, duB.x, duB.y};
            float tr[4];
            #pragma unroll
            for (int j = 3; j >= 0; j--) {
                u64 djd = dup2(ddj[j]);
                float2 eA = unp2(mul2(djd, A08));
                float2 eB = unp2(mul2(djd, A412));
                float4 bca = sBC[(CLEN - 1 - (s * 4 + (3 - j))) * 8 + n0];
                float4 bcb = sBC[(CLEN - 1 - (s * 4 + (3 - j))) * 8 + n0 + 4];
                h0  = fmaf(ex2(eA.x), h0,  duj[j] * bca.x);
                h8  = fmaf(ex2(eA.y), h8,  duj[j] * bca.z);
                h4  = fmaf(ex2(eB.x), h4,  duj[j] * bcb.x);
                h12 = fmaf(ex2(eB.y), h12, duj[j] * bcb.z);
                float t = fmaf(h12, bcb.w, fmaf(h4, bcb.y, fmaf(h8, bca.w, h0 * bca.y)));
                t += __shfl_xor_sync(0xffffffffu, t, 2);
                t += __shfl_xor_sync(0xffffffffu, t, 1);
                tr[j] = t;
            }
            if (n0 == 0) {
                u64 gux = mul2(up.x, Ddd), guy = mul2(up.y, Ddd);
                float2 g0 = unp2(gux), g1 = unp2(guy);
                yp4[-s] = make_float4(tr[0] + g0.x, tr[1] + g0.y,
                                      tr[2] + g1.x, tr[3] + g1.y);
            }
        }
    }
}

__global__ void __launch_bounds__(256, 5) k4c_scan(const float* __restrict__ alog,
                                                   const float* __restrict__ ds)
{
    __shared__ float4 sBC[1024];
    if (blockIdx.y == 0) k4c_body<false>(0, alog, ds, sBC);
    else                 k4c_body<true >(2, alog, ds, sBC);
}

// ================= K4t: transpose wh planes + merge all 4 into g_ysum =========
__global__ void k4t_merge()
{
    __shared__ float s1[64 * 65];
    __shared__ float s3[64 * 65];
    const int tid = threadIdx.x;
    const int b = blockIdx.x / DIN;
    const int d = blockIdx.x % DIN;
    const float4* p0 = (const float4*)(g_y + ((size_t)(0 * BATCH + b) * DIN + d) * LSEQ);
    const float4* p1 = (const float4*)(g_y + ((size_t)(1 * BATCH + b) * DIN + d) * LSEQ);
    const float4* p2 = (const float4*)(g_y + ((size_t)(2 * BATCH + b) * DIN + d) * LSEQ);
    const float4* p3 = (const float4*)(g_y + ((size_t)(3 * BATCH + b) * DIN + d) * LSEQ);

    for (int t4 = tid; t4 < 1024; t4 += 256) {
        int i = t4 * 4;
        int w_ = i >> 6, h0 = i & 63;
        float4 v1 = p1[t4], v3 = p3[t4];
        s1[(h0 + 0) * 65 + w_] = v1.x; s1[(h0 + 1) * 65 + w_] = v1.y;
        s1[(h0 + 2) * 65 + w_] = v1.z; s1[(h0 + 3) * 65 + w_] = v1.w;
        s3[(h0 + 0) * 65 + w_] = v3.x; s3[(h0 + 1) * 65 + w_] = v3.y;
        s3[(h0 + 2) * 65 + w_] = v3.z; s3[(h0 + 3) * 65 + w_] = v3.w;
    }
    __syncthreads();

    float4* po = (float4*)(g_ysum + (size_t)(b * DIN + d) * LSEQ);
    for (int t4 = tid; t4 < 1024; t4 += 256) {
        int j = t4 * 4;
        int h = j >> 6, w0 = j & 63;
        float4 a = p0[t4], c = p2[t4];
        float4 r;
        r.x = a.x + c.x + s1[h * 65 + w0 + 0] + s3[h * 65 + w0 + 0];
        r.y = a.y + c.y + s1[h * 65 + w0 + 1] + s3[h * 65 + w0 + 1];
        r.z = a.z + c.z + s1[h * 65 + w0 + 2] + s3[h * 65 + w0 + 2];
        r.w = a.w + c.w + s1[h * 65 + w0 + 3] + s3[h * 65 + w0 + 3];
        po[t4] = r;
    }
}

// ================= K5: out-LN + gate + out_proj + residual (16 px/block) =======
__global__ void __launch_bounds__(256, 8) k5_final(const float* __restrict__ onw,
                                                   const float* __restrict__ onb,
                                                   const float* __restrict__ wout,
                                                   float* __restrict__ out)
{
    extern __shared__ float sm[];
    float* yc = sm;                  // 192*20 (padded)
    const int tid = threadIdx.x, lane = tid & 31, warp = tid >> 5;
    const int b = blockIdx.x >> 8;
    const int l0 = (blockIdx.x & 255) << 4;

    for (int i = tid; i < 192 * 16; i += 256) {
        int d = i >> 4, p = i & 15;
        yc[d * 20 + p] = g_ysum[(size_t)(b * DIN + d) * LSEQ + l0 + p];
    }
    __syncthreads();

    #pragma unroll
    for (int pp = 0; pp < 2; pp++) {
        const int p = warp * 2 + pp;
        float s = 0.f, s2 = 0.f, vv[6];
        #pragma unroll
        for (int j = 0; j < 6; j++) {
            float v = yc[(lane + 32 * j) * 20 + p];
            vv[j] = v; s += v; s2 += v * v;
        }
        #pragma unroll
        for (int o = 16; o > 0; o >>= 1) {
            s  += __shfl_xor_sync(0xffffffffu, s,  o);
            s2 += __shfl_xor_sync(0xffffffffu, s2, o);
        }
        float mu = s * (1.f / 192.f);
        float var = s2 * (1.f / 192.f) - mu * mu;
        float rstd = rsqrtf(var + 1e-5f);
        size_t zbase = ((size_t)(b * LSEQ + l0 + p)) * DIN;
        #pragma unroll
        for (int j = 0; j < 6; j++) {
            int dd = lane + 32 * j;
            float g = (vv[j] - mu) * rstd * onw[dd] + onb[dd];
            yc[dd * 20 + p] = g * g_zs[zbase + dd];
        }
    }
    __syncthreads();

    const int og = tid >> 3;
    const int pg = tid & 7;
    u64 accp[3];
    accp[0] = accp[1] = accp[2] = 0ull;

    for (int dd4 = 0; dd4 < 192; dd4 += 4) {
        float4 w0 = __ldg((const float4*)(wout + (og * 3 + 0) * 192 + dd4));
        float4 w1 = __ldg((const float4*)(wout + (og * 3 + 1) * 192 + dd4));
        float4 w2 = __ldg((const float4*)(wout + (og * 3 + 2) * 192 + dd4));
        float w0a[4] = {w0.x, w0.y, w0.z, w0.w};
        float w1a[4] = {w1.x, w1.y, w1.z, w1.w};
        float w2a[4] = {w2.x, w2.y, w2.z, w2.w};
        #pragma unroll
        for (int j = 0; j < 4; j++) {
            u64 g = *(const u64*)&yc[(dd4 + j) * 20 + pg * 2];
            accp[0] = fma2(dup2(w0a[j]), g, accp[0]);
            accp[1] = fma2(dup2(w1a[j]), g, accp[1]);
            accp[2] = fma2(dup2(w2a[j]), g, accp[2]);
        }
    }
    __syncthreads();

    float* buf = sm;                 // 16 x 100 staging
    #pragma unroll
    for (int oi = 0; oi < 3; oi++) {
        float2 f = unp2(accp[oi]);
        buf[(pg * 2 + 0) * 100 + og * 3 + oi] = f.x;
        buf[(pg * 2 + 1) * 100 + og * 3 + oi] = f.y;
    }
    __syncthreads();

    const float4* df4 = (const float4*)(g_diff + ((size_t)b * LSEQ + l0) * CDIM);
    float4* out4 = (float4*)(out + ((size_t)b * LSEQ + l0) * CDIM);
    for (int t = tid; t < 16 * 24; t += 256) {
        int p = t / 24, o4 = t % 24;
        float4 v = *(const float4*)&buf[p * 100 + o4 * 4];
        float4 dv = df4[p * 24 + o4];
        v.x += dv.x; v.y += dv.y; v.z += dv.z; v.w += dv.w;
        out4[p * 24 + o4] = v;
    }
}

// ================= launch =================
extern "C" void kernel_launch(void* const* d_in, const int* in_sizes, int n_in,
                              void* d_out, int out_size)
{
    const float* x     = (const float*)d_in[0];
    const float* y     = (const float*)d_in[1];
    const float* ln_w  = (const float*)d_in[2];
    const float* ln_b  = (const float*)d_in[3];
    const float* ipw   = (const float*)d_in[4];
    const float* cw    = (const float*)d_in[5];
    const float* cb    = (const float*)d_in[6];
    const float* xpw   = (const float*)d_in[7];
    const float* dtw   = (const float*)d_in[8];
    const float* dtb   = (const float*)d_in[9];
    const float* alog  = (const float*)d_in[10];
    const float* ds    = (const float*)d_in[11];
    const float* onw   = (const float*)d_in[12];
    const float* onb   = (const float*)d_in[13];
    const float* wout  = (const float*)d_in[14];
    float* out = (float*)d_out;

    const int smem1 = (96 * 64 + 96 * 128) * 4;
    const int smem3 = (192 * 48 + 38 * 65 + 192 * 6 + 192) * 4;
    const int smem5 = (192 * 20) * 4;
    cudaFuncSetAttribute(k1_prologue, cudaFuncAttributeMaxDynamicSharedMemorySize, smem1);
    cudaFuncSetAttribute(k3_xproj,   cudaFuncAttributeMaxDynamicSharedMemorySize, smem3);
    cudaFuncSetAttribute(k5_final,   cudaFuncAttributeMaxDynamicSharedMemorySize, smem5);

    k1_prologue<<<dim3(128, 3), 256, smem1>>>(x, y, ln_w, ln_b, ipw);
    k2_conv<<<BATCH * DIN, 256>>>(cw, cb);
    k3_xproj<<<BATCH * 4 * (LSEQ / 64), 256, smem3>>>(xpw, dtw, dtb);
    k4a_scan<<<dim3(1536, 2), 256>>>(alog);
    k4b_carry<<<NCH * NST / 256, 256>>>();
    // k4c: 3 octet-blocks x 32 chunks x 2 kk x 2 b = 384 per direction
    k4c_scan<<<dim3(384, 2), 256>>>(alog, ds);
    k4t_merge<<<BATCH * DIN, 256>>>();
    k5_final<<<BATCH * (LSEQ / 16), 256, smem5>>>(onw, onb, wout, out);
}